// round 12
// baseline (speedup 1.0000x reference)
#include <cuda_runtime.h>
#include <cuda_bf16.h>
#include <cuda_fp16.h>
#include <math.h>
#include <cstdint>

#define NN 50000
#define NE 800000
#define NT 850000          // NE + NN self loops
#define HID 128
#define EPSV 1e-5f

// ================= scratch (device globals; no allocations) =================
__device__ __align__(16) float g_x [NN*HID];
__device__ __align__(16) float g_xr[NN*HID];
__device__ __align__(16) float g_h [NN*HID];
__device__ __align__(16) __half g_xlh[NN*HID];   // xl fp16 gather table
__device__ __align__(16) __half g_ahi[NN*HID];   // x split hi (fp16) - layer0 feed
__device__ __align__(16) __half g_alo[NN*HID];   // x split lo (fp16)
// weights fp16: 4 layers x [k=128][n=256] ([Wl|Wr]) + skip [k=128][n=128]
__device__ __align__(16) __half g_wh[4*32768 + 16384];
__device__ int   g_cnt[NN];
__device__ int   g_rowptr[NN+1];
__device__ int   g_fill[NN];
__device__ int   g_csrc[NT];
__device__ int   g_bsum[256];
__device__ int   g_bpre[256];
__device__ float g_stats[256];
__device__ float g_scale[HID];
__device__ float g_shift[HID];
__device__ int   g_ctr;

// ================= mma.sync helpers =================
__device__ __forceinline__ uint32_t smem_u32(const void* p){
  uint32_t a;
  asm("{ .reg .u64 t; cvta.to.shared.u64 t, %1; cvt.u32.u64 %0, t; }" : "=r"(a) : "l"(p));
  return a;
}
__device__ __forceinline__ void ldm4(uint32_t* r, uint32_t a){
  asm volatile("ldmatrix.sync.aligned.m8n8.x4.shared.b16 {%0,%1,%2,%3}, [%4];"
    : "=r"(r[0]),"=r"(r[1]),"=r"(r[2]),"=r"(r[3]) : "r"(a));
}
__device__ __forceinline__ void ldm4t(uint32_t* r, uint32_t a){
  asm volatile("ldmatrix.sync.aligned.m8n8.x4.trans.shared.b16 {%0,%1,%2,%3}, [%4];"
    : "=r"(r[0]),"=r"(r[1]),"=r"(r[2]),"=r"(r[3]) : "r"(a));
}
__device__ __forceinline__ void mma_f16(float* c, const uint32_t* a, const uint32_t* b){
  asm volatile("mma.sync.aligned.m16n8k16.row.col.f32.f16.f16.f32 "
    "{%0,%1,%2,%3}, {%4,%5,%6,%7}, {%8,%9}, {%0,%1,%2,%3};"
    : "+f"(c[0]),"+f"(c[1]),"+f"(c[2]),"+f"(c[3])
    : "r"(a[0]),"r"(a[1]),"r"(a[2]),"r"(a[3]), "r"(b[0]),"r"(b[1]));
}
__device__ __forceinline__ uint32_t swA(int r, int c2){
  int u = c2 >> 4;
  u = (u & 8) | ((u ^ (r & 7)) & 7);
  return (uint32_t)(r*256 + (u << 4) + (c2 & 15));
}
__device__ __forceinline__ uint32_t swB128(int r, int c2){   // B tile: 128 rows x 256B
  int u = c2 >> 4;
  u = (u & ~7) | ((u ^ (r & 7)) & 7);
  return (uint32_t)(r*256 + (u << 4) + (c2 & 15));
}

#define SM_ALO 32768
#define SM_B   65536
#define SMEM_TOT 98304      // 96 KB -> 2 CTAs/SM

// 2-term 128-col compute: D = Ahi@B + Alo@B.
__device__ __forceinline__ void mma_compute128(uint32_t sb, float acc[2][4][4], int wid, int lane){
  const int warp_m = wid >> 2, warp_n = wid & 3;
  const int arow = warp_m*32 + (lane & 15);
  const int ac2b = (lane >> 4) << 4;
  const int bgrp = lane >> 3;
  const int bkr  = ((bgrp & 1) << 3) + (lane & 7);
  const int bnc  = warp_n*32 + ((bgrp >> 1) << 3);

  #pragma unroll
  for(int ks = 0; ks < 8; ks++){
    uint32_t bf[4][2], tmp[4];
    #pragma unroll
    for(int np = 0; np < 2; np++){
      uint32_t boff = swB128(ks*16 + bkr, (bnc + np*16)*2);
      ldm4t(tmp, sb + SM_B + boff);
      bf[np*2][0]=tmp[0]; bf[np*2][1]=tmp[1]; bf[np*2+1][0]=tmp[2]; bf[np*2+1][1]=tmp[3];
    }
    uint32_t a[2][4];
    #pragma unroll
    for(int mt = 0; mt < 2; mt++)
      ldm4(a[mt], sb + swA(arow + mt*16, ks*32 + ac2b));
    #pragma unroll
    for(int mt = 0; mt < 2; mt++)
      #pragma unroll
      for(int nt = 0; nt < 4; nt++)
        mma_f16(acc[mt][nt], a[mt], bf[nt]);
    #pragma unroll
    for(int mt = 0; mt < 2; mt++)
      ldm4(a[mt], sb + SM_ALO + swA(arow + mt*16, ks*32 + ac2b));
    #pragma unroll
    for(int mt = 0; mt < 2; mt++)
      #pragma unroll
      for(int nt = 0; nt < 4; nt++)
        mma_f16(acc[mt][nt], a[mt], bf[nt]);
  }
}

__device__ __forceinline__ void fill_B128(char* smem, int tid,
  const __half* __restrict__ Wg, int stride, int col_off){
  for(int ch = tid; ch < 2048; ch += 512){
    int r = ch >> 4, c2 = (ch & 15) * 16;
    uint32_t off = swB128(r, c2);
    *(uint4*)(smem + SM_B + off) = *(const uint4*)(Wg + r*stride + col_off + (c2 >> 1));
  }
}

// epilogue for a 128-col pass: OUT=0 -> g_xlh (fp16), OUT=1 -> g_xr (fp32)
template<int OUT>
__device__ __forceinline__ void ep128(float acc[2][4][4], int bm, int wid, int lane){
  const int warp_m = wid >> 2, warp_n = wid & 3;
  #pragma unroll
  for(int mt = 0; mt < 2; mt++){
    int r0 = bm + warp_m*32 + mt*16 + (lane >> 2);
    #pragma unroll
    for(int nt = 0; nt < 4; nt++){
      int col = warp_n*32 + nt*8 + (lane & 3)*2;
      #pragma unroll
      for(int half = 0; half < 2; half++){
        int grow = r0 + half*8;
        if(grow >= NN) continue;
        float v0 = acc[mt][nt][half*2], v1 = acc[mt][nt][half*2+1];
        if(OUT == 0)
          *(__half2*)(g_xlh + grow*128 + col) = __floats2half2_rn(v0, v1);
        else
          *(float2*)(g_xr + grow*128 + col) = make_float2(v0, v1);
      }
    }
  }
}

#define ZERO_ACC(acc) { _Pragma("unroll") for(int mt=0;mt<2;mt++) _Pragma("unroll") for(int nt=0;nt<4;nt++) _Pragma("unroll") for(int r=0;r<4;r++) acc[mt][nt][r]=0.f; }

// ================= setup =================
__global__ void k_cvt_w(const float* __restrict__ Wl, const float* __restrict__ Wr,
                        const float* __restrict__ skW){
  int i = blockIdx.x*blockDim.x + threadIdx.x;
  if(i < NN) g_cnt[i] = 0;
  if(i >= 4*32768 + 16384) return;
  float v;
  if(i < 4*32768){
    int l = i >> 15, rem = i & 32767, k = rem >> 8, n = rem & 255;
    v = (n < 128) ? Wl[l*16384 + k*128 + n] : Wr[l*16384 + k*128 + (n-128)];
  } else {
    v = skW[i - 4*32768];
  }
  g_wh[i] = __float2half_rn(v);
}
__global__ void k_initcount(const float* __restrict__ x, const int* __restrict__ ei){
  int i = blockIdx.x*blockDim.x + threadIdx.x;
  if(i < NT){
    int d = (i < NE) ? ei[NE + i] : (i - NE);
    atomicAdd(&g_cnt[d], 1);
  }
  if(i >= NN*32) return;
  float4 v = ((const float4*)x)[i];
  ((float4*)g_x)[i] = v;
  __half2 h0, h1, l0, l1;
  h0.x = __float2half_rn(v.x); h0.y = __float2half_rn(v.y);
  h1.x = __float2half_rn(v.z); h1.y = __float2half_rn(v.w);
  l0.x = __float2half_rn(v.x - __half2float(h0.x));
  l0.y = __float2half_rn(v.y - __half2float(h0.y));
  l1.x = __float2half_rn(v.z - __half2float(h1.x));
  l1.y = __float2half_rn(v.w - __half2float(h1.y));
  ((__half2*)g_ahi)[2*i] = h0; ((__half2*)g_ahi)[2*i+1] = h1;
  ((__half2*)g_alo)[2*i] = l0; ((__half2*)g_alo)[2*i+1] = l1;
}
#define SCAN_B 196
__global__ void k_blocksum(){
  __shared__ int sh[256];
  __shared__ int s_last;
  int t = threadIdx.x;
  int i = blockIdx.x*256 + t;
  sh[t] = (i < NN) ? g_cnt[i] : 0; __syncthreads();
  #pragma unroll
  for(int off = 128; off > 0; off >>= 1){
    if(t < off) sh[t] += sh[t+off];
    __syncthreads();
  }
  if(t == 0) g_bsum[blockIdx.x] = sh[0];
  __threadfence();
  if(t == 0){
    int v = atomicAdd(&g_ctr, 1);
    s_last = (v == (int)gridDim.x - 1);
  }
  __syncthreads();
  if(s_last){
    int v = (t < SCAN_B) ? g_bsum[t] : 0;
    sh[t] = v; __syncthreads();
    #pragma unroll
    for(int off = 1; off < 256; off <<= 1){
      int u = (t >= off) ? sh[t-off] : 0;
      __syncthreads(); sh[t] += u; __syncthreads();
    }
    if(t < SCAN_B) g_bpre[t] = sh[t] - v;
    if(t == 255) g_rowptr[NN] = sh[255];
    if(t == 0) g_ctr = 0;
  }
}
__global__ void k_rowptr(){
  __shared__ int sh[256];
  int t = threadIdx.x;
  int i = blockIdx.x*256 + t;
  int v = (i < NN) ? g_cnt[i] : 0;
  sh[t] = v; __syncthreads();
  #pragma unroll
  for(int off = 1; off < 256; off <<= 1){
    int u = (t >= off) ? sh[t-off] : 0;
    __syncthreads(); sh[t] += u; __syncthreads();
  }
  if(i < NN){
    int e = sh[t] - v + g_bpre[blockIdx.x];
    g_rowptr[i] = e; g_fill[i] = e;
  }
}
__global__ void k_scatter(const int* __restrict__ ei){
  int i = blockIdx.x*blockDim.x + threadIdx.x;
  if(i >= NT) return;
  int s, d;
  if(i < NE){ s = ei[i]; d = ei[NE + i]; }
  else      { s = d = i - NE; }
  int pos = atomicAdd(&g_fill[d], 1);
  g_csrc[pos] = s;
}

// ================= layer-0 LR GEMM (two 128-col passes, 96KB smem) =================
__global__ void __launch_bounds__(512, 2) k_mma_lr0(){
  extern __shared__ __align__(16) char smem[];
  const int tid = threadIdx.x, wid = tid >> 5, lane = tid & 31;
  const int bm = blockIdx.x * 128;
  const uint32_t sb = smem_u32(smem);
  for(int ch = tid; ch < 2048; ch += 512){
    int r = ch >> 4, c2 = (ch & 15) << 4;
    int grow = bm + r;
    uint32_t off = swA(r, c2);
    uint4 vh = make_uint4(0,0,0,0), vl = vh;
    if(grow < NN){
      vh = *(const uint4*)(g_ahi + grow*128 + (c2 >> 1));
      vl = *(const uint4*)(g_alo + grow*128 + (c2 >> 1));
    }
    *(uint4*)(smem + off)          = vh;
    *(uint4*)(smem + SM_ALO + off) = vl;
  }
  fill_B128(smem, tid, g_wh, 256, 0);         // Wl half
  __syncthreads();
  float acc[2][4][4];
  ZERO_ACC(acc);
  mma_compute128(sb, acc, wid, lane);
  ep128<0>(acc, bm, wid, lane);
  __syncthreads();
  fill_B128(smem, tid, g_wh, 256, 128);       // Wr half
  __syncthreads();
  ZERO_ACC(acc);
  mma_compute128(sb, acc, wid, lane);
  ep128<1>(acc, bm, wid, lane);
}

// ================= fused skip-GEMM (+ next-layer LR GEMM, or final FC) =================
template<bool DO_LR>
__global__ void __launch_bounds__(512, 2) k_fused(const float* __restrict__ bias, int next_layer,
                                                  const float* __restrict__ fw,
                                                  const float* __restrict__ fb,
                                                  float* __restrict__ out){
  extern __shared__ __align__(16) char smem[];
  const int tid = threadIdx.x, wid = tid >> 5, lane = tid & 31;
  const int bm = blockIdx.x * 128;
  const uint32_t sb = smem_u32(smem);

  for(int ch = tid; ch < 2048; ch += 512){
    int r = ch >> 4, c2 = (ch & 15) << 4;
    int grow = bm + r;
    uint32_t off = swA(r, c2);
    int c = c2 >> 1;
    __half2 hh[4], ll[4];
    if(grow < NN){
      #pragma unroll
      for(int q = 0; q < 2; q++){
        float4 v  = *(const float4*)(g_h + grow*128 + c + q*4);
        float4 sc = *(const float4*)(g_scale + c + q*4);
        float4 sh = *(const float4*)(g_shift + c + q*4);
        float z0 = fmaf(v.x, sc.x, sh.x); z0 = z0 > 0.f ? z0 : (__expf(z0) - 1.f);
        float z1 = fmaf(v.y, sc.y, sh.y); z1 = z1 > 0.f ? z1 : (__expf(z1) - 1.f);
        float z2 = fmaf(v.z, sc.z, sh.z); z2 = z2 > 0.f ? z2 : (__expf(z2) - 1.f);
        float z3 = fmaf(v.w, sc.w, sh.w); z3 = z3 > 0.f ? z3 : (__expf(z3) - 1.f);
        hh[q*2].x   = __float2half_rn(z0); hh[q*2].y   = __float2half_rn(z1);
        hh[q*2+1].x = __float2half_rn(z2); hh[q*2+1].y = __float2half_rn(z3);
        ll[q*2].x   = __float2half_rn(z0 - __half2float(hh[q*2].x));
        ll[q*2].y   = __float2half_rn(z1 - __half2float(hh[q*2].y));
        ll[q*2+1].x = __float2half_rn(z2 - __half2float(hh[q*2+1].x));
        ll[q*2+1].y = __float2half_rn(z3 - __half2float(hh[q*2+1].y));
      }
    } else {
      #pragma unroll
      for(int q = 0; q < 4; q++){ hh[q].x = hh[q].y = __float2half_rn(0.f); ll[q] = hh[q]; }
    }
    *(uint4*)(smem + off)          = *(uint4*)hh;
    *(uint4*)(smem + SM_ALO + off) = *(uint4*)ll;
  }
  fill_B128(smem, tid, g_wh + 4*32768, 128, 0);
  __syncthreads();

  {
    float acc[2][4][4];
    ZERO_ACC(acc);
    mma_compute128(sb, acc, wid, lane);
    __syncthreads();

    const int warp_m = wid >> 2, warp_n = wid & 3;
    #pragma unroll
    for(int mt = 0; mt < 2; mt++){
      int rloc0 = warp_m*32 + mt*16 + (lane >> 2);
      #pragma unroll
      for(int nt = 0; nt < 4; nt++){
        int col = warp_n*32 + nt*8 + (lane & 3)*2;
        #pragma unroll
        for(int half = 0; half < 2; half++){
          int rloc = rloc0 + half*8;
          int grow = bm + rloc;
          float v0 = acc[mt][nt][half*2], v1 = acc[mt][nt][half*2+1];
          if(grow < NN){
            float2 old = *(const float2*)(g_x + grow*128 + col);
            v0 += bias[col]   + old.x;
            v1 += bias[col+1] + old.y;
            *(float2*)(g_x + grow*128 + col) = make_float2(v0, v1);
          } else { v0 = 0.f; v1 = 0.f; }
          if(DO_LR){
            __half2 h, l;
            h.x = __float2half_rn(v0); h.y = __float2half_rn(v1);
            l.x = __float2half_rn(v0 - __half2float(h.x));
            l.y = __float2half_rn(v1 - __half2float(h.y));
            uint32_t off = swA(rloc, col*2);
            *(__half2*)(smem + off)          = h;
            *(__half2*)(smem + SM_ALO + off) = l;
          }
        }
      }
    }
  }
  if(!DO_LR){
    __syncthreads();
    int row = bm + (tid >> 2);
    int part = tid & 3;
    int rowc = row < NN ? row : (NN - 1);
    const float4* xp = (const float4*)(g_x + rowc*128 + part*32);
    float s = 0.f;
    #pragma unroll
    for(int q = 0; q < 8; q++){
      float4 v = xp[q];
      float4 w = *(const float4*)(fw + part*32 + q*4);
      s += v.x*w.x + v.y*w.y + v.z*w.z + v.w*w.w;
    }
    s += __shfl_xor_sync(0xffffffffu, s, 1);
    s += __shfl_xor_sync(0xffffffffu, s, 2);
    if(part == 0 && row < NN) out[row] = s + fb[0];
    return;
  }

  const __half* wlr = g_wh + next_layer*32768;
  __syncthreads();
  fill_B128(smem, tid, wlr, 256, 0);
  __syncthreads();
  {
    float acc[2][4][4];
    ZERO_ACC(acc);
    mma_compute128(sb, acc, wid, lane);
    ep128<0>(acc, bm, wid, lane);
  }
  __syncthreads();
  fill_B128(smem, tid, wlr, 256, 128);
  __syncthreads();
  {
    float acc[2][4][4];
    ZERO_ACC(acc);
    mma_compute128(sb, acc, wid, lane);
    ep128<1>(acc, bm, wid, lane);
  }
}

// ================= GATv2: 2 nodes per warp, interleaved chains =================
__device__ __forceinline__ float lrelu(float v){ return v > 0.f ? v : 0.2f*v; }

// grid = NN/16 = 3125 blocks exactly; every node index valid.
__global__ void __launch_bounds__(256) k_gat(const float* __restrict__ att,
                                             const float* __restrict__ convb,
                                             const float* __restrict__ gnw,
                                             const float* __restrict__ gnb,
                                             const float* __restrict__ gnms){
  __shared__ float s_sum[8][128];
  __shared__ float s_sq [8][128];
  __shared__ int s_last;
  int tid = threadIdx.x, wid = tid >> 5, lane = tid & 31;
  int n0 = blockIdx.x*16 + wid*2;         // n0, n0+1 both < NN (50000 = 3125*16)
  int c4 = lane * 4;

  const float4 at4 = *(const float4*)(att + c4);
  const float4 xrA = *(const float4*)(g_xr + n0*128 + c4);
  const float4 xrB = *(const float4*)(g_xr + (n0+1)*128 + c4);
  int pb0 = g_rowptr[n0], pb1 = g_rowptr[n0+1], pe1 = g_rowptr[n0+2];
  const int K0 = pb1 - pb0, K1 = pe1 - pb1;   // both >= 1 (self loops)
  const int K = max(K0, K1);

  float m0 = -3.4e38f, ds0 = 0.f, a00 = 0.f, a01 = 0.f, a02 = 0.f, a03 = 0.f;
  float m1 = -3.4e38f, ds1 = 0.f, a10 = 0.f, a11 = 0.f, a12 = 0.f, a13 = 0.f;

  int p0 = pb0, p1 = pb1;
  int s0 = g_csrc[p0], s1 = g_csrc[p1];
  uint2 raw0 = *(const uint2*)(g_xlh + s0*128 + c4);
  uint2 raw1 = *(const uint2*)(g_xlh + s1*128 + c4);

  for(int it = 0; it < K; it++){
    uint2 cur0 = raw0, cur1 = raw1;
    // prefetch next (clamped; safe reads)
    int pn0 = (it+1 < K0) ? p0+1 : pb0;
    int pn1 = (it+1 < K1) ? p1+1 : pb1;
    if(it+1 < K){
      int t0i = g_csrc[pn0], t1i = g_csrc[pn1];
      raw0 = *(const uint2*)(g_xlh + t0i*128 + c4);
      raw1 = *(const uint2*)(g_xlh + t1i*128 + c4);
    }
    p0 = pn0; p1 = pn1;

    float2 e00 = __half22float2(*(__half2*)&cur0.x);
    float2 e01 = __half22float2(*(__half2*)&cur0.y);
    float2 e10 = __half22float2(*(__half2*)&cur1.x);
    float2 e11 = __half22float2(*(__half2*)&cur1.y);

    float t0 = lrelu(e00.x + xrA.x)*at4.x + lrelu(e00.y + xrA.y)*at4.y
             + lrelu(e01.x + xrA.z)*at4.z + lrelu(e01.y + xrA.w)*at4.w;
    float t1 = lrelu(e10.x + xrB.x)*at4.x + lrelu(e10.y + xrB.y)*at4.y
             + lrelu(e11.x + xrB.z)*at4.z + lrelu(e11.y + xrB.w)*at4.w;
    t0 += __shfl_xor_sync(0xffffffffu, t0, 4);
    t1 += __shfl_xor_sync(0xffffffffu, t1, 4);
    t0 += __shfl_xor_sync(0xffffffffu, t0, 2);
    t1 += __shfl_xor_sync(0xffffffffu, t1, 2);
    t0 += __shfl_xor_sync(0xffffffffu, t0, 1);
    t1 += __shfl_xor_sync(0xffffffffu, t1, 1);
    if(it >= K0) t0 = -3.4e38f;     // invalid tail -> exact no-op update
    if(it >= K1) t1 = -3.4e38f;

    float mn0 = fmaxf(m0, t0);
    float fo0 = __expf(m0 - mn0), fn0 = __expf(t0 - mn0);
    ds0 = fmaf(ds0, fo0, fn0);
    a00 = fmaf(a00, fo0, fn0*e00.x); a01 = fmaf(a01, fo0, fn0*e00.y);
    a02 = fmaf(a02, fo0, fn0*e01.x); a03 = fmaf(a03, fo0, fn0*e01.y);
    m0 = mn0;

    float mn1 = fmaxf(m1, t1);
    float fo1 = __expf(m1 - mn1), fn1 = __expf(t1 - mn1);
    ds1 = fmaf(ds1, fo1, fn1);
    a10 = fmaf(a10, fo1, fn1*e10.x); a11 = fmaf(a11, fo1, fn1*e10.y);
    a12 = fmaf(a12, fo1, fn1*e11.x); a13 = fmaf(a13, fo1, fn1*e11.y);
    m1 = mn1;
  }

  const float4 bb = *(const float4*)(convb + c4);
  float inv0 = 1.f / ds0, inv1 = 1.f / ds1;
  float4 o0, o1;
  o0.x = fmaf(a00, inv0, bb.x); o0.y = fmaf(a01, inv0, bb.y);
  o0.z = fmaf(a02, inv0, bb.z); o0.w = fmaf(a03, inv0, bb.w);
  o1.x = fmaf(a10, inv1, bb.x); o1.y = fmaf(a11, inv1, bb.y);
  o1.z = fmaf(a12, inv1, bb.z); o1.w = fmaf(a13, inv1, bb.w);
  *(float4*)(g_h + n0*128 + c4)     = o0;
  *(float4*)(g_h + (n0+1)*128 + c4) = o1;

  s_sum[wid][c4]   = o0.x + o1.x;  s_sum[wid][c4+1] = o0.y + o1.y;
  s_sum[wid][c4+2] = o0.z + o1.z;  s_sum[wid][c4+3] = o0.w + o1.w;
  s_sq [wid][c4]   = o0.x*o0.x + o1.x*o1.x;
  s_sq [wid][c4+1] = o0.y*o0.y + o1.y*o1.y;
  s_sq [wid][c4+2] = o0.z*o0.z + o1.z*o1.z;
  s_sq [wid][c4+3] = o0.w*o0.w + o1.w*o1.w;
  __syncthreads();
  if(tid < 128){
    float s = 0.f, q = 0.f;
    #pragma unroll
    for(int w = 0; w < 8; w++){ s += s_sum[w][tid]; q += s_sq[w][tid]; }
    atomicAdd(&g_stats[tid], s);
    atomicAdd(&g_stats[128 + tid], q);
  }
  __threadfence();
  if(tid == 0){
    int v = atomicAdd(&g_ctr, 1);
    s_last = (v == (int)gridDim.x - 1);
  }
  __syncthreads();
  if(s_last){
    if(tid < 128){
      float sum = g_stats[tid], sq = g_stats[128 + tid];
      float mean = sum * (1.f/(float)NN);
      float mv = gnms[tid] * mean;
      float var = sq * (1.f/(float)NN) - 2.f*mv*mean + mv*mv;
      float sc = gnw[tid] * rsqrtf(var + EPSV);
      g_scale[tid] = sc;
      g_shift[tid] = gnb[tid] - mv*sc;
      g_stats[tid] = 0.f; g_stats[128 + tid] = 0.f;
    }
    if(tid == 0) g_ctr = 0;
  }
}

// ================= launcher =================
extern "C" void kernel_launch(void* const* d_in, const int* in_sizes, int n_in,
                              void* d_out, int out_size){
  const float* x     = (const float*)d_in[0];
  const int*   ei    = (const int*)  d_in[1];
  const float* Wl    = (const float*)d_in[2];
  const float* Wr    = (const float*)d_in[3];
  const float* att   = (const float*)d_in[4];
  const float* convb = (const float*)d_in[5];
  const float* gnw   = (const float*)d_in[6];
  const float* gnb   = (const float*)d_in[7];
  const float* gnms  = (const float*)d_in[8];
  const float* skW   = (const float*)d_in[9];
  const float* skb   = (const float*)d_in[10];
  const float* fcW   = (const float*)d_in[11];
  const float* fcb   = (const float*)d_in[12];
  float* out = (float*)d_out;

  static int cfg_done = 0;
  if(!cfg_done){
    cudaFuncSetAttribute(k_mma_lr0,      cudaFuncAttributeMaxDynamicSharedMemorySize, SMEM_TOT);
    cudaFuncSetAttribute(k_fused<true>,  cudaFuncAttributeMaxDynamicSharedMemorySize, SMEM_TOT);
    cudaFuncSetAttribute(k_fused<false>, cudaFuncAttributeMaxDynamicSharedMemorySize, SMEM_TOT);
    cfg_done = 1;
  }

  k_cvt_w    <<<(4*32768 + 16384 + 255)/256, 256>>>(Wl, Wr, skW);
  k_initcount<<<(NN*32 + 255)/256, 256>>>(x, ei);
  k_blocksum <<<SCAN_B, 256>>>();
  k_rowptr   <<<SCAN_B, 256>>>();
  k_scatter  <<<(NT + 255)/256, 256>>>(ei);

  const int MMA_GRID = (NN + 127)/128;       // 391
  const int GAT_GRID = NN/16;                // 3125 (exact)
  k_mma_lr0<<<MMA_GRID, 512, SMEM_TOT>>>();
  for(int l = 0; l < 4; l++){
    k_gat<<<GAT_GRID, 256>>>(att + l*HID, convb + l*HID,
                             gnw + l*HID, gnb + l*HID, gnms + l*HID);
    if(l < 3) k_fused<true> <<<MMA_GRID, 512, SMEM_TOT>>>(skb, l + 1, nullptr, nullptr, nullptr);
    else      k_fused<false><<<MMA_GRID, 512, SMEM_TOT>>>(skb, 0, fcW, fcb, out);
  }
}

// round 13
// speedup vs baseline: 1.1642x; 1.1642x over previous
#include <cuda_runtime.h>
#include <cuda_bf16.h>
#include <cuda_fp16.h>
#include <math.h>
#include <cstdint>

#define NN 50000
#define NE 800000
#define NT 850000          // NE + NN self loops
#define HID 128
#define EPSV 1e-5f

// ================= scratch (device globals; no allocations) =================
__device__ __align__(16) float g_x [NN*HID];
__device__ __align__(16) float g_xr[NN*HID];
__device__ __align__(16) float g_h [NN*HID];
__device__ __align__(16) __half g_xlh[NN*HID];   // xl fp16 gather table
__device__ __align__(16) __half g_ahi[NN*HID];   // x split hi (fp16) - layer0 feed
__device__ __align__(16) __half g_alo[NN*HID];   // x split lo (fp16)
// weights fp16: 4 layers x [k=128][n=256] ([Wl|Wr]) + skip [k=128][n=128]
__device__ __align__(16) __half g_wh[4*32768 + 16384];
__device__ int   g_cnt[NN];        // zero at load; re-zeroed by k_csr each call
__device__ int   g_rowptr[NN+1];
__device__ int   g_fill[NN];
__device__ int   g_csrc[NT];
__device__ int   g_bsum[256];
__device__ int   g_bpre[256];
__device__ float g_stats[256];
__device__ float g_scale[HID];
__device__ float g_shift[HID];
__device__ int   g_ctr;
__device__ int   g_c1, g_c2, g_c3;
__device__ volatile int g_flagA;

// ================= mma.sync helpers =================
__device__ __forceinline__ uint32_t smem_u32(const void* p){
  uint32_t a;
  asm("{ .reg .u64 t; cvta.to.shared.u64 t, %1; cvt.u32.u64 %0, t; }" : "=r"(a) : "l"(p));
  return a;
}
__device__ __forceinline__ void ldm4(uint32_t* r, uint32_t a){
  asm volatile("ldmatrix.sync.aligned.m8n8.x4.shared.b16 {%0,%1,%2,%3}, [%4];"
    : "=r"(r[0]),"=r"(r[1]),"=r"(r[2]),"=r"(r[3]) : "r"(a));
}
__device__ __forceinline__ void ldm4t(uint32_t* r, uint32_t a){
  asm volatile("ldmatrix.sync.aligned.m8n8.x4.trans.shared.b16 {%0,%1,%2,%3}, [%4];"
    : "=r"(r[0]),"=r"(r[1]),"=r"(r[2]),"=r"(r[3]) : "r"(a));
}
__device__ __forceinline__ void mma_f16(float* c, const uint32_t* a, const uint32_t* b){
  asm volatile("mma.sync.aligned.m16n8k16.row.col.f32.f16.f16.f32 "
    "{%0,%1,%2,%3}, {%4,%5,%6,%7}, {%8,%9}, {%0,%1,%2,%3};"
    : "+f"(c[0]),"+f"(c[1]),"+f"(c[2]),"+f"(c[3])
    : "r"(a[0]),"r"(a[1]),"r"(a[2]),"r"(a[3]), "r"(b[0]),"r"(b[1]));
}
__device__ __forceinline__ uint32_t swA(int r, int c2){
  int u = c2 >> 4;
  u = (u & 8) | ((u ^ (r & 7)) & 7);
  return (uint32_t)(r*256 + (u << 4) + (c2 & 15));
}
__device__ __forceinline__ uint32_t swB128(int r, int c2){   // B tile: 128 rows x 256B
  int u = c2 >> 4;
  u = (u & ~7) | ((u ^ (r & 7)) & 7);
  return (uint32_t)(r*256 + (u << 4) + (c2 & 15));
}

#define SM_ALO 32768
#define SM_B   65536
#define SMEM_TOT 98304      // 96 KB -> 2 CTAs/SM

// 2-term 128-col compute: D = Ahi@B + Alo@B.
__device__ __forceinline__ void mma_compute128(uint32_t sb, float acc[2][4][4], int wid, int lane){
  const int warp_m = wid >> 2, warp_n = wid & 3;
  const int arow = warp_m*32 + (lane & 15);
  const int ac2b = (lane >> 4) << 4;
  const int bgrp = lane >> 3;
  const int bkr  = ((bgrp & 1) << 3) + (lane & 7);
  const int bnc  = warp_n*32 + ((bgrp >> 1) << 3);

  #pragma unroll
  for(int ks = 0; ks < 8; ks++){
    uint32_t bf[4][2], tmp[4];
    #pragma unroll
    for(int np = 0; np < 2; np++){
      uint32_t boff = swB128(ks*16 + bkr, (bnc + np*16)*2);
      ldm4t(tmp, sb + SM_B + boff);
      bf[np*2][0]=tmp[0]; bf[np*2][1]=tmp[1]; bf[np*2+1][0]=tmp[2]; bf[np*2+1][1]=tmp[3];
    }
    uint32_t a[2][4];
    #pragma unroll
    for(int mt = 0; mt < 2; mt++)
      ldm4(a[mt], sb + swA(arow + mt*16, ks*32 + ac2b));
    #pragma unroll
    for(int mt = 0; mt < 2; mt++)
      #pragma unroll
      for(int nt = 0; nt < 4; nt++)
        mma_f16(acc[mt][nt], a[mt], bf[nt]);
    #pragma unroll
    for(int mt = 0; mt < 2; mt++)
      ldm4(a[mt], sb + SM_ALO + swA(arow + mt*16, ks*32 + ac2b));
    #pragma unroll
    for(int mt = 0; mt < 2; mt++)
      #pragma unroll
      for(int nt = 0; nt < 4; nt++)
        mma_f16(acc[mt][nt], a[mt], bf[nt]);
  }
}

__device__ __forceinline__ void fill_B128(char* smem, int tid,
  const __half* __restrict__ Wg, int stride, int col_off){
  for(int ch = tid; ch < 2048; ch += 512){
    int r = ch >> 4, c2 = (ch & 15) * 16;
    uint32_t off = swB128(r, c2);
    *(uint4*)(smem + SM_B + off) = *(const uint4*)(Wg + r*stride + col_off + (c2 >> 1));
  }
}

// epilogue for a 128-col pass: OUT=0 -> g_xlh (fp16), OUT=1 -> g_xr (fp32)
template<int OUT>
__device__ __forceinline__ void ep128(float acc[2][4][4], int bm, int wid, int lane){
  const int warp_m = wid >> 2, warp_n = wid & 3;
  #pragma unroll
  for(int mt = 0; mt < 2; mt++){
    int r0 = bm + warp_m*32 + mt*16 + (lane >> 2);
    #pragma unroll
    for(int nt = 0; nt < 4; nt++){
      int col = warp_n*32 + nt*8 + (lane & 3)*2;
      #pragma unroll
      for(int half = 0; half < 2; half++){
        int grow = r0 + half*8;
        if(grow >= NN) continue;
        float v0 = acc[mt][nt][half*2], v1 = acc[mt][nt][half*2+1];
        if(OUT == 0)
          *(__half2*)(g_xlh + grow*128 + col) = __floats2half2_rn(v0, v1);
        else
          *(float2*)(g_xr + grow*128 + col) = make_float2(v0, v1);
      }
    }
  }
}

#define ZERO_ACC(acc) { _Pragma("unroll") for(int mt=0;mt<2;mt++) _Pragma("unroll") for(int nt=0;nt<4;nt++) _Pragma("unroll") for(int r=0;r<4;r++) acc[mt][nt][r]=0.f; }

// ================= setup =================
__global__ void k_cvt_w(const float* __restrict__ Wl, const float* __restrict__ Wr,
                        const float* __restrict__ skW){
  int i = blockIdx.x*blockDim.x + threadIdx.x;
  if(i >= 4*32768 + 16384) return;
  float v;
  if(i < 4*32768){
    int l = i >> 15, rem = i & 32767, k = rem >> 8, n = rem & 255;
    v = (n < 128) ? Wl[l*16384 + k*128 + n] : Wr[l*16384 + k*128 + (n-128)];
  } else {
    v = skW[i - 4*32768];
  }
  g_wh[i] = __float2half_rn(v);
}
// x copy + fp16 splits + edge count (g_cnt zeroed at load / by previous k_csr)
__global__ void k_initcount(const float* __restrict__ x, const int* __restrict__ ei){
  int i = blockIdx.x*blockDim.x + threadIdx.x;
  if(i < NT){
    int d = (i < NE) ? ei[NE + i] : (i - NE);
    atomicAdd(&g_cnt[d], 1);
  }
  if(i >= NN*32) return;
  float4 v = ((const float4*)x)[i];
  ((float4*)g_x)[i] = v;
  __half2 h0, h1, l0, l1;
  h0.x = __float2half_rn(v.x); h0.y = __float2half_rn(v.y);
  h1.x = __float2half_rn(v.z); h1.y = __float2half_rn(v.w);
  l0.x = __float2half_rn(v.x - __half2float(h0.x));
  l0.y = __float2half_rn(v.y - __half2float(h0.y));
  l1.x = __float2half_rn(v.z - __half2float(h1.x));
  l1.y = __float2half_rn(v.w - __half2float(h1.y));
  ((__half2*)g_ahi)[2*i] = h0; ((__half2*)g_ahi)[2*i+1] = h1;
  ((__half2*)g_alo)[2*i] = l0; ((__half2*)g_alo)[2*i+1] = l1;
}

#define SCAN_B 196
// merged CSR build: blocksum -> (last-block scan) -> rowptr -> scatter -> reset.
// 196 co-resident blocks; counter/flag grid syncs.
__global__ void __launch_bounds__(256) k_csr(const int* __restrict__ ei){
  __shared__ int sh[256];
  __shared__ int s_last;
  const int t = threadIdx.x, b = blockIdx.x;
  const int i = b*256 + t;
  const int myc = (i < NN) ? g_cnt[i] : 0;

  // ---- phase 1: block sums ----
  sh[t] = myc; __syncthreads();
  #pragma unroll
  for(int off = 128; off > 0; off >>= 1){
    if(t < off) sh[t] += sh[t+off];
    __syncthreads();
  }
  if(t == 0){
    g_bsum[b] = sh[0];
    __threadfence();
    int v = atomicAdd(&g_c1, 1);
    s_last = (v == SCAN_B - 1);
  }
  __syncthreads();
  if(s_last){
    int v = (t < SCAN_B) ? g_bsum[t] : 0;
    sh[t] = v; __syncthreads();
    #pragma unroll
    for(int off = 1; off < 256; off <<= 1){
      int u = (t >= off) ? sh[t-off] : 0;
      __syncthreads(); sh[t] += u; __syncthreads();
    }
    if(t < SCAN_B) g_bpre[t] = sh[t] - v;
    if(t == 255) g_rowptr[NN] = sh[255];
    __syncthreads();
    if(t == 0){ __threadfence(); g_flagA = 1; }
  }
  if(t == 0){ while(g_flagA == 0){} }
  __syncthreads();

  // ---- phase 2: rowptr (block exclusive scan + block prefix) ----
  sh[t] = myc; __syncthreads();
  #pragma unroll
  for(int off = 1; off < 256; off <<= 1){
    int u = (t >= off) ? sh[t-off] : 0;
    __syncthreads(); sh[t] += u; __syncthreads();
  }
  if(i < NN){
    int e = sh[t] - myc + g_bpre[b];
    g_rowptr[i] = e; g_fill[i] = e;
  }
  if(t == 0){
    __threadfence();
    atomicAdd(&g_c2, 1);
    while(atomicAdd(&g_c2, 0) < SCAN_B){}
  }
  __syncthreads();

  // ---- phase 3: scatter (grid-stride) ----
  for(int e = b*256 + t; e < NT; e += SCAN_B*256){
    int s, d;
    if(e < NE){ s = ei[e]; d = ei[NE + e]; }
    else      { s = d = e - NE; }
    int pos = atomicAdd(&g_fill[d], 1);
    g_csrc[pos] = s;
  }

  // ---- phase 4: zero g_cnt for next call + reset sync state ----
  if(i < NN) g_cnt[i] = 0;
  __threadfence();
  __syncthreads();
  if(t == 0){
    int v = atomicAdd(&g_c3, 1);
    if(v == SCAN_B - 1){ g_c1 = 0; g_c2 = 0; g_c3 = 0; g_flagA = 0; }
  }
}

// ================= layer-0 LR GEMM (two 128-col passes, 96KB smem) =================
__global__ void __launch_bounds__(512, 2) k_mma_lr0(){
  extern __shared__ __align__(16) char smem[];
  const int tid = threadIdx.x, wid = tid >> 5, lane = tid & 31;
  const int bm = blockIdx.x * 128;
  const uint32_t sb = smem_u32(smem);
  for(int ch = tid; ch < 2048; ch += 512){
    int r = ch >> 4, c2 = (ch & 15) << 4;
    int grow = bm + r;
    uint32_t off = swA(r, c2);
    uint4 vh = make_uint4(0,0,0,0), vl = vh;
    if(grow < NN){
      vh = *(const uint4*)(g_ahi + grow*128 + (c2 >> 1));
      vl = *(const uint4*)(g_alo + grow*128 + (c2 >> 1));
    }
    *(uint4*)(smem + off)          = vh;
    *(uint4*)(smem + SM_ALO + off) = vl;
  }
  fill_B128(smem, tid, g_wh, 256, 0);         // Wl half
  __syncthreads();
  float acc[2][4][4];
  ZERO_ACC(acc);
  mma_compute128(sb, acc, wid, lane);
  ep128<0>(acc, bm, wid, lane);
  __syncthreads();
  fill_B128(smem, tid, g_wh, 256, 128);       // Wr half
  __syncthreads();
  ZERO_ACC(acc);
  mma_compute128(sb, acc, wid, lane);
  ep128<1>(acc, bm, wid, lane);
}

// ================= fused skip-GEMM (+ next-layer LR GEMM, or final FC) =================
template<bool DO_LR>
__global__ void __launch_bounds__(512, 2) k_fused(const float* __restrict__ bias, int next_layer,
                                                  const float* __restrict__ fw,
                                                  const float* __restrict__ fb,
                                                  float* __restrict__ out){
  extern __shared__ __align__(16) char smem[];
  const int tid = threadIdx.x, wid = tid >> 5, lane = tid & 31;
  const int bm = blockIdx.x * 128;
  const uint32_t sb = smem_u32(smem);

  for(int ch = tid; ch < 2048; ch += 512){
    int r = ch >> 4, c2 = (ch & 15) << 4;
    int grow = bm + r;
    uint32_t off = swA(r, c2);
    int c = c2 >> 1;
    __half2 hh[4], ll[4];
    if(grow < NN){
      #pragma unroll
      for(int q = 0; q < 2; q++){
        float4 v  = *(const float4*)(g_h + grow*128 + c + q*4);
        float4 sc = *(const float4*)(g_scale + c + q*4);
        float4 sh = *(const float4*)(g_shift + c + q*4);
        float z0 = fmaf(v.x, sc.x, sh.x); z0 = z0 > 0.f ? z0 : (__expf(z0) - 1.f);
        float z1 = fmaf(v.y, sc.y, sh.y); z1 = z1 > 0.f ? z1 : (__expf(z1) - 1.f);
        float z2 = fmaf(v.z, sc.z, sh.z); z2 = z2 > 0.f ? z2 : (__expf(z2) - 1.f);
        float z3 = fmaf(v.w, sc.w, sh.w); z3 = z3 > 0.f ? z3 : (__expf(z3) - 1.f);
        hh[q*2].x   = __float2half_rn(z0); hh[q*2].y   = __float2half_rn(z1);
        hh[q*2+1].x = __float2half_rn(z2); hh[q*2+1].y = __float2half_rn(z3);
        ll[q*2].x   = __float2half_rn(z0 - __half2float(hh[q*2].x));
        ll[q*2].y   = __float2half_rn(z1 - __half2float(hh[q*2].y));
        ll[q*2+1].x = __float2half_rn(z2 - __half2float(hh[q*2+1].x));
        ll[q*2+1].y = __float2half_rn(z3 - __half2float(hh[q*2+1].y));
      }
    } else {
      #pragma unroll
      for(int q = 0; q < 4; q++){ hh[q].x = hh[q].y = __float2half_rn(0.f); ll[q] = hh[q]; }
    }
    *(uint4*)(smem + off)          = *(uint4*)hh;
    *(uint4*)(smem + SM_ALO + off) = *(uint4*)ll;
  }
  fill_B128(smem, tid, g_wh + 4*32768, 128, 0);
  __syncthreads();

  {
    float acc[2][4][4];
    ZERO_ACC(acc);
    mma_compute128(sb, acc, wid, lane);
    __syncthreads();

    const int warp_m = wid >> 2, warp_n = wid & 3;
    #pragma unroll
    for(int mt = 0; mt < 2; mt++){
      int rloc0 = warp_m*32 + mt*16 + (lane >> 2);
      #pragma unroll
      for(int nt = 0; nt < 4; nt++){
        int col = warp_n*32 + nt*8 + (lane & 3)*2;
        #pragma unroll
        for(int half = 0; half < 2; half++){
          int rloc = rloc0 + half*8;
          int grow = bm + rloc;
          float v0 = acc[mt][nt][half*2], v1 = acc[mt][nt][half*2+1];
          if(grow < NN){
            float2 old = *(const float2*)(g_x + grow*128 + col);
            v0 += bias[col]   + old.x;
            v1 += bias[col+1] + old.y;
            *(float2*)(g_x + grow*128 + col) = make_float2(v0, v1);
          } else { v0 = 0.f; v1 = 0.f; }
          if(DO_LR){
            __half2 h, l;
            h.x = __float2half_rn(v0); h.y = __float2half_rn(v1);
            l.x = __float2half_rn(v0 - __half2float(h.x));
            l.y = __float2half_rn(v1 - __half2float(h.y));
            uint32_t off = swA(rloc, col*2);
            *(__half2*)(smem + off)          = h;
            *(__half2*)(smem + SM_ALO + off) = l;
          }
        }
      }
    }
  }
  if(!DO_LR){
    __syncthreads();
    int row = bm + (tid >> 2);
    int part = tid & 3;
    int rowc = row < NN ? row : (NN - 1);
    const float4* xp = (const float4*)(g_x + rowc*128 + part*32);
    float s = 0.f;
    #pragma unroll
    for(int q = 0; q < 8; q++){
      float4 v = xp[q];
      float4 w = *(const float4*)(fw + part*32 + q*4);
      s += v.x*w.x + v.y*w.y + v.z*w.z + v.w*w.w;
    }
    s += __shfl_xor_sync(0xffffffffu, s, 1);
    s += __shfl_xor_sync(0xffffffffu, s, 2);
    if(part == 0 && row < NN) out[row] = s + fb[0];
    return;
  }

  const __half* wlr = g_wh + next_layer*32768;
  __syncthreads();
  fill_B128(smem, tid, wlr, 256, 0);
  __syncthreads();
  {
    float acc[2][4][4];
    ZERO_ACC(acc);
    mma_compute128(sb, acc, wid, lane);
    ep128<0>(acc, bm, wid, lane);
  }
  __syncthreads();
  fill_B128(smem, tid, wlr, 256, 128);
  __syncthreads();
  {
    float acc[2][4][4];
    ZERO_ACC(acc);
    mma_compute128(sb, acc, wid, lane);
    ep128<1>(acc, bm, wid, lane);
  }
}

// ================= GATv2 (proven round-10 form) + fused GraphNorm =================
__device__ __forceinline__ float lrelu(float v){ return v > 0.f ? v : 0.2f*v; }

__global__ void __launch_bounds__(256) k_gat(const float* __restrict__ att,
                                             const float* __restrict__ convb,
                                             const float* __restrict__ gnw,
                                             const float* __restrict__ gnb,
                                             const float* __restrict__ gnms){
  __shared__ float s_sum[8][128];
  __shared__ float s_sq [8][128];
  __shared__ int s_last;
  int tid = threadIdx.x, wid = tid >> 5, lane = tid & 31;
  int node = blockIdx.x*8 + wid;
  int c4 = lane * 4;
  float4 o = make_float4(0.f, 0.f, 0.f, 0.f);

  if(node < NN){
    const float4 xr4 = *(const float4*)(g_xr + node*128 + c4);
    const float4 at4 = *(const float4*)(att + c4);
    int pb = g_rowptr[node], pe = g_rowptr[node+1];

    float m = -3.4e38f, ds = 0.f;
    float a0 = 0.f, a1 = 0.f, a2 = 0.f, a3 = 0.f;

    if(pb < pe){
      int sA = g_csrc[pb];
      uint2 rawN = *(const uint2*)(g_xlh + sA*128 + c4);
      int sB = (pb+1 < pe) ? g_csrc[pb+1] : 0;
      for(int p = pb; p < pe; p++){
        uint2 raw = rawN;
        if(p+1 < pe){
          rawN = *(const uint2*)(g_xlh + sB*128 + c4);
          if(p+2 < pe) sB = g_csrc[p+2];
        }
        float2 f0 = __half22float2(*(__half2*)&raw.x);
        float2 f1 = __half22float2(*(__half2*)&raw.y);
        float t = lrelu(f0.x + xr4.x)*at4.x + lrelu(f0.y + xr4.y)*at4.y
                + lrelu(f1.x + xr4.z)*at4.z + lrelu(f1.y + xr4.w)*at4.w;
        t += __shfl_xor_sync(0xffffffffu, t, 4);
        t += __shfl_xor_sync(0xffffffffu, t, 2);
        t += __shfl_xor_sync(0xffffffffu, t, 1);
        if(t <= m){
          float a = __expf(t - m);
          ds += a;
          a0 = fmaf(a, f0.x, a0); a1 = fmaf(a, f0.y, a1);
          a2 = fmaf(a, f1.x, a2); a3 = fmaf(a, f1.y, a3);
        } else {
          float f = __expf(m - t);
          ds = fmaf(ds, f, 1.f);
          a0 = fmaf(a0, f, f0.x); a1 = fmaf(a1, f, f0.y);
          a2 = fmaf(a2, f, f1.x); a3 = fmaf(a3, f, f1.y);
          m = t;
        }
      }
    }
    float inv = 1.f / ds;
    const float4 bb = *(const float4*)(convb + c4);
    o.x = fmaf(a0, inv, bb.x); o.y = fmaf(a1, inv, bb.y);
    o.z = fmaf(a2, inv, bb.z); o.w = fmaf(a3, inv, bb.w);
    *(float4*)(g_h + node*128 + c4) = o;
  }

  s_sum[wid][c4]   = o.x;     s_sum[wid][c4+1] = o.y;
  s_sum[wid][c4+2] = o.z;     s_sum[wid][c4+3] = o.w;
  s_sq [wid][c4]   = o.x*o.x; s_sq [wid][c4+1] = o.y*o.y;
  s_sq [wid][c4+2] = o.z*o.z; s_sq [wid][c4+3] = o.w*o.w;
  __syncthreads();
  if(tid < 128){
    float s = 0.f, q = 0.f;
    #pragma unroll
    for(int w = 0; w < 8; w++){ s += s_sum[w][tid]; q += s_sq[w][tid]; }
    atomicAdd(&g_stats[tid], s);
    atomicAdd(&g_stats[128 + tid], q);
  }
  __threadfence();
  if(tid == 0){
    int v = atomicAdd(&g_ctr, 1);
    s_last = (v == (int)gridDim.x - 1);
  }
  __syncthreads();
  if(s_last){
    if(tid < 128){
      float sum = g_stats[tid], sq = g_stats[128 + tid];
      float mean = sum * (1.f/(float)NN);
      float mv = gnms[tid] * mean;
      float var = sq * (1.f/(float)NN) - 2.f*mv*mean + mv*mv;
      float sc = gnw[tid] * rsqrtf(var + EPSV);
      g_scale[tid] = sc;
      g_shift[tid] = gnb[tid] - mv*sc;
      g_stats[tid] = 0.f; g_stats[128 + tid] = 0.f;
    }
    if(tid == 0) g_ctr = 0;
  }
}

// ================= launcher =================
extern "C" void kernel_launch(void* const* d_in, const int* in_sizes, int n_in,
                              void* d_out, int out_size){
  const float* x     = (const float*)d_in[0];
  const int*   ei    = (const int*)  d_in[1];
  const float* Wl    = (const float*)d_in[2];
  const float* Wr    = (const float*)d_in[3];
  const float* att   = (const float*)d_in[4];
  const float* convb = (const float*)d_in[5];
  const float* gnw   = (const float*)d_in[6];
  const float* gnb   = (const float*)d_in[7];
  const float* gnms  = (const float*)d_in[8];
  const float* skW   = (const float*)d_in[9];
  const float* skb   = (const float*)d_in[10];
  const float* fcW   = (const float*)d_in[11];
  const float* fcb   = (const float*)d_in[12];
  float* out = (float*)d_out;

  static int cfg_done = 0;
  if(!cfg_done){
    cudaFuncSetAttribute(k_mma_lr0,      cudaFuncAttributeMaxDynamicSharedMemorySize, SMEM_TOT);
    cudaFuncSetAttribute(k_fused<true>,  cudaFuncAttributeMaxDynamicSharedMemorySize, SMEM_TOT);
    cudaFuncSetAttribute(k_fused<false>, cudaFuncAttributeMaxDynamicSharedMemorySize, SMEM_TOT);
    cfg_done = 1;
  }

  k_cvt_w    <<<(4*32768 + 16384 + 255)/256, 256>>>(Wl, Wr, skW);
  k_initcount<<<(NN*32 + 255)/256, 256>>>(x, ei);
  k_csr      <<<SCAN_B, 256>>>(ei);

  const int MMA_GRID = (NN + 127)/128;       // 391
  const int GAT_GRID = (NN + 7)/8;           // 6250
  k_mma_lr0<<<MMA_GRID, 512, SMEM_TOT>>>();
  for(int l = 0; l < 4; l++){
    k_gat<<<GAT_GRID, 256>>>(att + l*HID, convb + l*HID,
                             gnw + l*HID, gnb + l*HID, gnms + l*HID);
    if(l < 3) k_fused<true> <<<MMA_GRID, 512, SMEM_TOT>>>(skb, l + 1, nullptr, nullptr, nullptr);
    else      k_fused<false><<<MMA_GRID, 512, SMEM_TOT>>>(skb, 0, fcW, fcb, out);
  }
}

// round 14
// speedup vs baseline: 1.1816x; 1.0150x over previous
#include <cuda_runtime.h>
#include <cuda_bf16.h>
#include <cuda_fp16.h>
#include <math.h>
#include <cstdint>

#define NN 50000
#define NE 800000
#define NT 850000          // NE + NN self loops
#define HID 128
#define EPSV 1e-5f

// ================= scratch (device globals; no allocations) =================
__device__ __align__(16) float g_x [NN*HID];
__device__ __align__(16) float g_xr[NN*HID];
__device__ __align__(16) float g_h [NN*HID];
__device__ __align__(16) __half g_xlh[NN*HID];   // xl fp16 gather table
__device__ __align__(16) __half g_ahi[NN*HID];   // x split hi (fp16) - layer0 feed
__device__ __align__(16) __half g_alo[NN*HID];   // x split lo (fp16)
// weights fp16: 4 layers x [k=128][n=256] ([Wl|Wr]) + skip [k=128][n=128]
__device__ __align__(16) __half g_wh[4*32768 + 16384];
__device__ int   g_cnt[NN];     // zero at load; re-zeroed by k_fused<false> each call
__device__ int   g_rowptr[NN+1];
__device__ int   g_fill[NN];
__device__ int   g_csrc[NT];
__device__ int   g_bsum[256];
__device__ int   g_bpre[256];
__device__ float g_stats[256];
__device__ float g_scale[HID];
__device__ float g_shift[HID];
__device__ int   g_ctr;

// ================= mma.sync helpers =================
__device__ __forceinline__ uint32_t smem_u32(const void* p){
  uint32_t a;
  asm("{ .reg .u64 t; cvta.to.shared.u64 t, %1; cvt.u32.u64 %0, t; }" : "=r"(a) : "l"(p));
  return a;
}
__device__ __forceinline__ void ldm4(uint32_t* r, uint32_t a){
  asm volatile("ldmatrix.sync.aligned.m8n8.x4.shared.b16 {%0,%1,%2,%3}, [%4];"
    : "=r"(r[0]),"=r"(r[1]),"=r"(r[2]),"=r"(r[3]) : "r"(a));
}
__device__ __forceinline__ void ldm4t(uint32_t* r, uint32_t a){
  asm volatile("ldmatrix.sync.aligned.m8n8.x4.trans.shared.b16 {%0,%1,%2,%3}, [%4];"
    : "=r"(r[0]),"=r"(r[1]),"=r"(r[2]),"=r"(r[3]) : "r"(a));
}
__device__ __forceinline__ void mma_f16(float* c, const uint32_t* a, const uint32_t* b){
  asm volatile("mma.sync.aligned.m16n8k16.row.col.f32.f16.f16.f32 "
    "{%0,%1,%2,%3}, {%4,%5,%6,%7}, {%8,%9}, {%0,%1,%2,%3};"
    : "+f"(c[0]),"+f"(c[1]),"+f"(c[2]),"+f"(c[3])
    : "r"(a[0]),"r"(a[1]),"r"(a[2]),"r"(a[3]), "r"(b[0]),"r"(b[1]));
}
__device__ __forceinline__ uint32_t swA(int r, int c2){
  int u = c2 >> 4;
  u = (u & 8) | ((u ^ (r & 7)) & 7);
  return (uint32_t)(r*256 + (u << 4) + (c2 & 15));
}
__device__ __forceinline__ uint32_t swB128(int r, int c2){   // B tile: 128 rows x 256B
  int u = c2 >> 4;
  u = (u & ~7) | ((u ^ (r & 7)) & 7);
  return (uint32_t)(r*256 + (u << 4) + (c2 & 15));
}

#define SM_ALO 32768
#define SM_B   65536
#define SMEM_TOT 98304      // 96 KB -> 2 CTAs/SM

// 2-term 128-col compute: D = Ahi@B + Alo@B.
__device__ __forceinline__ void mma_compute128(uint32_t sb, float acc[2][4][4], int wid, int lane){
  const int warp_m = wid >> 2, warp_n = wid & 3;
  const int arow = warp_m*32 + (lane & 15);
  const int ac2b = (lane >> 4) << 4;
  const int bgrp = lane >> 3;
  const int bkr  = ((bgrp & 1) << 3) + (lane & 7);
  const int bnc  = warp_n*32 + ((bgrp >> 1) << 3);

  #pragma unroll
  for(int ks = 0; ks < 8; ks++){
    uint32_t bf[4][2], tmp[4];
    #pragma unroll
    for(int np = 0; np < 2; np++){
      uint32_t boff = swB128(ks*16 + bkr, (bnc + np*16)*2);
      ldm4t(tmp, sb + SM_B + boff);
      bf[np*2][0]=tmp[0]; bf[np*2][1]=tmp[1]; bf[np*2+1][0]=tmp[2]; bf[np*2+1][1]=tmp[3];
    }
    uint32_t a[2][4];
    #pragma unroll
    for(int mt = 0; mt < 2; mt++)
      ldm4(a[mt], sb + swA(arow + mt*16, ks*32 + ac2b));
    #pragma unroll
    for(int mt = 0; mt < 2; mt++)
      #pragma unroll
      for(int nt = 0; nt < 4; nt++)
        mma_f16(acc[mt][nt], a[mt], bf[nt]);
    #pragma unroll
    for(int mt = 0; mt < 2; mt++)
      ldm4(a[mt], sb + SM_ALO + swA(arow + mt*16, ks*32 + ac2b));
    #pragma unroll
    for(int mt = 0; mt < 2; mt++)
      #pragma unroll
      for(int nt = 0; nt < 4; nt++)
        mma_f16(acc[mt][nt], a[mt], bf[nt]);
  }
}

__device__ __forceinline__ void fill_B128(char* smem, int tid,
  const __half* __restrict__ Wg, int stride, int col_off){
  for(int ch = tid; ch < 2048; ch += 512){
    int r = ch >> 4, c2 = (ch & 15) * 16;
    uint32_t off = swB128(r, c2);
    *(uint4*)(smem + SM_B + off) = *(const uint4*)(Wg + r*stride + col_off + (c2 >> 1));
  }
}

// epilogue for a 128-col pass: OUT=0 -> g_xlh (fp16), OUT=1 -> g_xr (fp32)
template<int OUT>
__device__ __forceinline__ void ep128(float acc[2][4][4], int bm, int wid, int lane){
  const int warp_m = wid >> 2, warp_n = wid & 3;
  #pragma unroll
  for(int mt = 0; mt < 2; mt++){
    int r0 = bm + warp_m*32 + mt*16 + (lane >> 2);
    #pragma unroll
    for(int nt = 0; nt < 4; nt++){
      int col = warp_n*32 + nt*8 + (lane & 3)*2;
      #pragma unroll
      for(int half = 0; half < 2; half++){
        int grow = r0 + half*8;
        if(grow >= NN) continue;
        float v0 = acc[mt][nt][half*2], v1 = acc[mt][nt][half*2+1];
        if(OUT == 0)
          *(__half2*)(g_xlh + grow*128 + col) = __floats2half2_rn(v0, v1);
        else
          *(float2*)(g_xr + grow*128 + col) = make_float2(v0, v1);
      }
    }
  }
}

#define ZERO_ACC(acc) { _Pragma("unroll") for(int mt=0;mt<2;mt++) _Pragma("unroll") for(int nt=0;nt<4;nt++) _Pragma("unroll") for(int r=0;r<4;r++) acc[mt][nt][r]=0.f; }

// ================= setup: weights->fp16 + x copy/split + edge count =================
__global__ void k_setup(const float* __restrict__ x, const int* __restrict__ ei,
                        const float* __restrict__ Wl, const float* __restrict__ Wr,
                        const float* __restrict__ skW){
  int i = blockIdx.x*blockDim.x + threadIdx.x;
  if(i < 4*32768 + 16384){
    float v;
    if(i < 4*32768){
      int l = i >> 15, rem = i & 32767, k = rem >> 8, n = rem & 255;
      v = (n < 128) ? Wl[l*16384 + k*128 + n] : Wr[l*16384 + k*128 + (n-128)];
    } else {
      v = skW[i - 4*32768];
    }
    g_wh[i] = __float2half_rn(v);
  }
  if(i < NT){
    int d = (i < NE) ? ei[NE + i] : (i - NE);
    atomicAdd(&g_cnt[d], 1);
  }
  if(i >= NN*32) return;
  float4 v = ((const float4*)x)[i];
  ((float4*)g_x)[i] = v;
  __half2 h0, h1, l0, l1;
  h0.x = __float2half_rn(v.x); h0.y = __float2half_rn(v.y);
  h1.x = __float2half_rn(v.z); h1.y = __float2half_rn(v.w);
  l0.x = __float2half_rn(v.x - __half2float(h0.x));
  l0.y = __float2half_rn(v.y - __half2float(h0.y));
  l1.x = __float2half_rn(v.z - __half2float(h1.x));
  l1.y = __float2half_rn(v.w - __half2float(h1.y));
  ((__half2*)g_ahi)[2*i] = h0; ((__half2*)g_ahi)[2*i+1] = h1;
  ((__half2*)g_alo)[2*i] = l0; ((__half2*)g_alo)[2*i+1] = l1;
}
#define SCAN_B 196
__global__ void k_blocksum(){
  __shared__ int sh[256];
  __shared__ int s_last;
  int t = threadIdx.x;
  int i = blockIdx.x*256 + t;
  sh[t] = (i < NN) ? g_cnt[i] : 0; __syncthreads();
  #pragma unroll
  for(int off = 128; off > 0; off >>= 1){
    if(t < off) sh[t] += sh[t+off];
    __syncthreads();
  }
  if(t == 0) g_bsum[blockIdx.x] = sh[0];
  __threadfence();
  if(t == 0){
    int v = atomicAdd(&g_ctr, 1);
    s_last = (v == (int)gridDim.x - 1);
  }
  __syncthreads();
  if(s_last){
    int v = (t < SCAN_B) ? g_bsum[t] : 0;
    sh[t] = v; __syncthreads();
    #pragma unroll
    for(int off = 1; off < 256; off <<= 1){
      int u = (t >= off) ? sh[t-off] : 0;
      __syncthreads(); sh[t] += u; __syncthreads();
    }
    if(t < SCAN_B) g_bpre[t] = sh[t] - v;
    if(t == 255) g_rowptr[NN] = sh[255];
    if(t == 0) g_ctr = 0;
  }
}
__global__ void k_rowptr(){
  __shared__ int sh[256];
  int t = threadIdx.x;
  int i = blockIdx.x*256 + t;
  int v = (i < NN) ? g_cnt[i] : 0;
  sh[t] = v; __syncthreads();
  #pragma unroll
  for(int off = 1; off < 256; off <<= 1){
    int u = (t >= off) ? sh[t-off] : 0;
    __syncthreads(); sh[t] += u; __syncthreads();
  }
  if(i < NN){
    int e = sh[t] - v + g_bpre[blockIdx.x];
    g_rowptr[i] = e; g_fill[i] = e;
  }
}
__global__ void k_scatter(const int* __restrict__ ei){
  int i = blockIdx.x*blockDim.x + threadIdx.x;
  if(i >= NT) return;
  int s, d;
  if(i < NE){ s = ei[i]; d = ei[NE + i]; }
  else      { s = d = i - NE; }
  int pos = atomicAdd(&g_fill[d], 1);
  g_csrc[pos] = s;
}

// ================= layer-0 LR GEMM (two 128-col passes, 96KB smem) =================
__global__ void __launch_bounds__(512, 2) k_mma_lr0(){
  extern __shared__ __align__(16) char smem[];
  const int tid = threadIdx.x, wid = tid >> 5, lane = tid & 31;
  const int bm = blockIdx.x * 128;
  const uint32_t sb = smem_u32(smem);
  for(int ch = tid; ch < 2048; ch += 512){
    int r = ch >> 4, c2 = (ch & 15) << 4;
    int grow = bm + r;
    uint32_t off = swA(r, c2);
    uint4 vh = make_uint4(0,0,0,0), vl = vh;
    if(grow < NN){
      vh = *(const uint4*)(g_ahi + grow*128 + (c2 >> 1));
      vl = *(const uint4*)(g_alo + grow*128 + (c2 >> 1));
    }
    *(uint4*)(smem + off)          = vh;
    *(uint4*)(smem + SM_ALO + off) = vl;
  }
  fill_B128(smem, tid, g_wh, 256, 0);         // Wl half
  __syncthreads();
  float acc[2][4][4];
  ZERO_ACC(acc);
  mma_compute128(sb, acc, wid, lane);
  __syncthreads();                            // B reads complete
  ep128<0>(acc, bm, wid, lane);               // overlap: epilogue stores ...
  fill_B128(smem, tid, g_wh, 256, 128);       // ... with Wr-half B fill
  __syncthreads();
  ZERO_ACC(acc);
  mma_compute128(sb, acc, wid, lane);
  ep128<1>(acc, bm, wid, lane);
}

// ================= fused skip-GEMM (+ next-layer LR GEMM, or final FC) =================
template<bool DO_LR>
__global__ void __launch_bounds__(512, 2) k_fused(const float* __restrict__ bias, int next_layer,
                                                  const float* __restrict__ fw,
                                                  const float* __restrict__ fb,
                                                  float* __restrict__ out){
  extern __shared__ __align__(16) char smem[];
  const int tid = threadIdx.x, wid = tid >> 5, lane = tid & 31;
  const int bm = blockIdx.x * 128;
  const uint32_t sb = smem_u32(smem);

  // ---- prologue: A = fp16split(normelu(h)), B = skW ----
  for(int ch = tid; ch < 2048; ch += 512){
    int r = ch >> 4, c2 = (ch & 15) << 4;
    int grow = bm + r;
    uint32_t off = swA(r, c2);
    int c = c2 >> 1;
    __half2 hh[4], ll[4];
    if(grow < NN){
      #pragma unroll
      for(int q = 0; q < 2; q++){
        float4 v  = *(const float4*)(g_h + grow*128 + c + q*4);
        float4 sc = *(const float4*)(g_scale + c + q*4);
        float4 sh = *(const float4*)(g_shift + c + q*4);
        float z0 = fmaf(v.x, sc.x, sh.x); z0 = z0 > 0.f ? z0 : (__expf(z0) - 1.f);
        float z1 = fmaf(v.y, sc.y, sh.y); z1 = z1 > 0.f ? z1 : (__expf(z1) - 1.f);
        float z2 = fmaf(v.z, sc.z, sh.z); z2 = z2 > 0.f ? z2 : (__expf(z2) - 1.f);
        float z3 = fmaf(v.w, sc.w, sh.w); z3 = z3 > 0.f ? z3 : (__expf(z3) - 1.f);
        hh[q*2].x   = __float2half_rn(z0); hh[q*2].y   = __float2half_rn(z1);
        hh[q*2+1].x = __float2half_rn(z2); hh[q*2+1].y = __float2half_rn(z3);
        ll[q*2].x   = __float2half_rn(z0 - __half2float(hh[q*2].x));
        ll[q*2].y   = __float2half_rn(z1 - __half2float(hh[q*2].y));
        ll[q*2+1].x = __float2half_rn(z2 - __half2float(hh[q*2+1].x));
        ll[q*2+1].y = __float2half_rn(z3 - __half2float(hh[q*2+1].y));
      }
    } else {
      #pragma unroll
      for(int q = 0; q < 4; q++){ hh[q].x = hh[q].y = __float2half_rn(0.f); ll[q] = hh[q]; }
    }
    *(uint4*)(smem + off)          = *(uint4*)hh;
    *(uint4*)(smem + SM_ALO + off) = *(uint4*)ll;
  }
  fill_B128(smem, tid, g_wh + 4*32768, 128, 0);
  __syncthreads();

  // ---- skip GEMM ----
  {
    float acc[2][4][4];
    ZERO_ACC(acc);
    mma_compute128(sb, acc, wid, lane);
    __syncthreads();               // A/B reads complete

    // ---- epilogue: x update + new A splits into SMEM, overlapped with Wl B fill ----
    const int warp_m = wid >> 2, warp_n = wid & 3;
    #pragma unroll
    for(int mt = 0; mt < 2; mt++){
      int rloc0 = warp_m*32 + mt*16 + (lane >> 2);
      #pragma unroll
      for(int nt = 0; nt < 4; nt++){
        int col = warp_n*32 + nt*8 + (lane & 3)*2;
        #pragma unroll
        for(int half = 0; half < 2; half++){
          int rloc = rloc0 + half*8;
          int grow = bm + rloc;
          float v0 = acc[mt][nt][half*2], v1 = acc[mt][nt][half*2+1];
          if(grow < NN){
            float2 old = *(const float2*)(g_x + grow*128 + col);
            v0 += bias[col]   + old.x;
            v1 += bias[col+1] + old.y;
            *(float2*)(g_x + grow*128 + col) = make_float2(v0, v1);
          } else { v0 = 0.f; v1 = 0.f; }
          if(DO_LR){
            __half2 h, l;
            h.x = __float2half_rn(v0); h.y = __float2half_rn(v1);
            l.x = __float2half_rn(v0 - __half2float(h.x));
            l.y = __float2half_rn(v1 - __half2float(h.y));
            uint32_t off = swA(rloc, col*2);
            *(__half2*)(smem + off)          = h;
            *(__half2*)(smem + SM_ALO + off) = l;
          }
        }
      }
    }
    if(DO_LR)
      fill_B128(smem, tid, g_wh + next_layer*32768, 256, 0);  // Wl half, overlapped
  }
  if(!DO_LR){
    // ---- fused final FC + g_cnt re-zero for next call ----
    __syncthreads();
    int row = bm + (tid >> 2);
    int part = tid & 3;
    int rowc = row < NN ? row : (NN - 1);
    const float4* xp = (const float4*)(g_x + rowc*128 + part*32);
    float s = 0.f;
    #pragma unroll
    for(int q = 0; q < 8; q++){
      float4 v = xp[q];
      float4 w = *(const float4*)(fw + part*32 + q*4);
      s += v.x*w.x + v.y*w.y + v.z*w.z + v.w*w.w;
    }
    s += __shfl_xor_sync(0xffffffffu, s, 1);
    s += __shfl_xor_sync(0xffffffffu, s, 2);
    if(part == 0 && row < NN) out[row] = s + fb[0];
    for(int i = blockIdx.x*512 + tid; i < NN; i += gridDim.x*512)
      g_cnt[i] = 0;
    return;
  }

  __syncthreads();                 // A rewrite + B(Wl) fill visible
  {
    float acc[2][4][4];
    ZERO_ACC(acc);
    mma_compute128(sb, acc, wid, lane);
    __syncthreads();               // B reads complete
    ep128<0>(acc, bm, wid, lane);  // overlap epilogue with Wr B fill
    fill_B128(smem, tid, g_wh + next_layer*32768, 256, 128);
  }
  __syncthreads();
  {
    float acc[2][4][4];
    ZERO_ACC(acc);
    mma_compute128(sb, acc, wid, lane);
    ep128<1>(acc, bm, wid, lane);
  }
}

// ================= GATv2 (proven round-10 form) + fused GraphNorm =================
__device__ __forceinline__ float lrelu(float v){ return v > 0.f ? v : 0.2f*v; }

__global__ void __launch_bounds__(256) k_gat(const float* __restrict__ att,
                                             const float* __restrict__ convb,
                                             const float* __restrict__ gnw,
                                             const float* __restrict__ gnb,
                                             const float* __restrict__ gnms){
  __shared__ float s_sum[8][128];
  __shared__ float s_sq [8][128];
  __shared__ int s_last;
  int tid = threadIdx.x, wid = tid >> 5, lane = tid & 31;
  int node = blockIdx.x*8 + wid;
  int c4 = lane * 4;
  float4 o = make_float4(0.f, 0.f, 0.f, 0.f);

  if(node < NN){
    const float4 xr4 = *(const float4*)(g_xr + node*128 + c4);
    const float4 at4 = *(const float4*)(att + c4);
    int pb = g_rowptr[node], pe = g_rowptr[node+1];

    float m = -3.4e38f, ds = 0.f;
    float a0 = 0.f, a1 = 0.f, a2 = 0.f, a3 = 0.f;

    if(pb < pe){
      int sA = g_csrc[pb];
      uint2 rawN = *(const uint2*)(g_xlh + sA*128 + c4);
      int sB = (pb+1 < pe) ? g_csrc[pb+1] : 0;
      for(int p = pb; p < pe; p++){
        uint2 raw = rawN;
        if(p+1 < pe){
          rawN = *(const uint2*)(g_xlh + sB*128 + c4);
          if(p+2 < pe) sB = g_csrc[p+2];
        }
        float2 f0 = __half22float2(*(__half2*)&raw.x);
        float2 f1 = __half22float2(*(__half2*)&raw.y);
        float t = lrelu(f0.x + xr4.x)*at4.x + lrelu(f0.y + xr4.y)*at4.y
                + lrelu(f1.x + xr4.z)*at4.z + lrelu(f1.y + xr4.w)*at4.w;
        t += __shfl_xor_sync(0xffffffffu, t, 4);
        t += __shfl_xor_sync(0xffffffffu, t, 2);
        t += __shfl_xor_sync(0xffffffffu, t, 1);
        if(t <= m){
          float a = __expf(t - m);
          ds += a;
          a0 = fmaf(a, f0.x, a0); a1 = fmaf(a, f0.y, a1);
          a2 = fmaf(a, f1.x, a2); a3 = fmaf(a, f1.y, a3);
        } else {
          float f = __expf(m - t);
          ds = fmaf(ds, f, 1.f);
          a0 = fmaf(a0, f, f0.x); a1 = fmaf(a1, f, f0.y);
          a2 = fmaf(a2, f, f1.x); a3 = fmaf(a3, f, f1.y);
          m = t;
        }
      }
    }
    float inv = 1.f / ds;
    const float4 bb = *(const float4*)(convb + c4);
    o.x = fmaf(a0, inv, bb.x); o.y = fmaf(a1, inv, bb.y);
    o.z = fmaf(a2, inv, bb.z); o.w = fmaf(a3, inv, bb.w);
    *(float4*)(g_h + node*128 + c4) = o;
  }

  s_sum[wid][c4]   = o.x;     s_sum[wid][c4+1] = o.y;
  s_sum[wid][c4+2] = o.z;     s_sum[wid][c4+3] = o.w;
  s_sq [wid][c4]   = o.x*o.x; s_sq [wid][c4+1] = o.y*o.y;
  s_sq [wid][c4+2] = o.z*o.z; s_sq [wid][c4+3] = o.w*o.w;
  __syncthreads();
  if(tid < 128){
    float s = 0.f, q = 0.f;
    #pragma unroll
    for(int w = 0; w < 8; w++){ s += s_sum[w][tid]; q += s_sq[w][tid]; }
    atomicAdd(&g_stats[tid], s);
    atomicAdd(&g_stats[128 + tid], q);
  }
  __threadfence();
  if(tid == 0){
    int v = atomicAdd(&g_ctr, 1);
    s_last = (v == (int)gridDim.x - 1);
  }
  __syncthreads();
  if(s_last){
    if(tid < 128){
      float sum = g_stats[tid], sq = g_stats[128 + tid];
      float mean = sum * (1.f/(float)NN);
      float mv = gnms[tid] * mean;
      float var = sq * (1.f/(float)NN) - 2.f*mv*mean + mv*mv;
      float sc = gnw[tid] * rsqrtf(var + EPSV);
      g_scale[tid] = sc;
      g_shift[tid] = gnb[tid] - mv*sc;
      g_stats[tid] = 0.f; g_stats[128 + tid] = 0.f;
    }
    if(tid == 0) g_ctr = 0;
  }
}

// ================= launcher =================
extern "C" void kernel_launch(void* const* d_in, const int* in_sizes, int n_in,
                              void* d_out, int out_size){
  const float* x     = (const float*)d_in[0];
  const int*   ei    = (const int*)  d_in[1];
  const float* Wl    = (const float*)d_in[2];
  const float* Wr    = (const float*)d_in[3];
  const float* att   = (const float*)d_in[4];
  const float* convb = (const float*)d_in[5];
  const float* gnw   = (const float*)d_in[6];
  const float* gnb   = (const float*)d_in[7];
  const float* gnms  = (const float*)d_in[8];
  const float* skW   = (const float*)d_in[9];
  const float* skb   = (const float*)d_in[10];
  const float* fcW   = (const float*)d_in[11];
  const float* fcb   = (const float*)d_in[12];
  float* out = (float*)d_out;

  static int cfg_done = 0;
  if(!cfg_done){
    cudaFuncSetAttribute(k_mma_lr0,      cudaFuncAttributeMaxDynamicSharedMemorySize, SMEM_TOT);
    cudaFuncSetAttribute(k_fused<true>,  cudaFuncAttributeMaxDynamicSharedMemorySize, SMEM_TOT);
    cudaFuncSetAttribute(k_fused<false>, cudaFuncAttributeMaxDynamicSharedMemorySize, SMEM_TOT);
    cfg_done = 1;
  }

  k_setup   <<<(NN*32 + 255)/256, 256>>>(x, ei, Wl, Wr, skW);
  k_blocksum<<<SCAN_B, 256>>>();
  k_rowptr  <<<SCAN_B, 256>>>();
  k_scatter <<<(NT + 255)/256, 256>>>(ei);

  const int MMA_GRID = (NN + 127)/128;       // 391
  const int GAT_GRID = (NN + 7)/8;           // 6250
  k_mma_lr0<<<MMA_GRID, 512, SMEM_TOT>>>();
  for(int l = 0; l < 4; l++){
    k_gat<<<GAT_GRID, 256>>>(att + l*HID, convb + l*HID,
                             gnw + l*HID, gnb + l*HID, gnms + l*HID);
    if(l < 3) k_fused<true> <<<MMA_GRID, 512, SMEM_TOT>>>(skb, l + 1, nullptr, nullptr, nullptr);
    else      k_fused<false><<<MMA_GRID, 512, SMEM_TOT>>>(skb, 0, fcW, fcb, out);
  }
}

// round 15
// speedup vs baseline: 1.1963x; 1.0124x over previous
#include <cuda_runtime.h>
#include <cuda_bf16.h>
#include <cuda_fp16.h>
#include <math.h>
#include <cstdint>

#define NN 50000
#define NE 800000
#define NT 850000          // NE + NN self loops
#define HID 128
#define EPSV 1e-5f

// ================= scratch (device globals; no allocations) =================
__device__ __align__(16) float g_x [NN*HID];
__device__ __align__(16) float g_xr[NN*HID];
__device__ __align__(16) float g_h [NN*HID];
__device__ __align__(16) __half g_xlh[NN*HID];   // xl fp16 gather table
__device__ __align__(16) __half g_ahi[NN*HID];   // x split hi (fp16) - layer0 feed
__device__ __align__(16) __half g_alo[NN*HID];   // x split lo (fp16)
// weights fp16: 4 layers x [k=128][n=256] ([Wl|Wr]) + skip [k=128][n=128]
__device__ __align__(16) __half g_wh[4*32768 + 16384];
__device__ int   g_cnt[NN];     // zero at load; re-zeroed by k_fused<false> each call
__device__ int   g_rowptr[NN+1];
__device__ int   g_fill[NN];
__device__ int   g_csrc[NT];
__device__ int   g_bsum[256];
__device__ int   g_bpre[256];
__device__ float g_stats[256];
__device__ float g_scale[HID];
__device__ float g_shift[HID];
__device__ int   g_ctr;

// ================= mma.sync helpers =================
__device__ __forceinline__ uint32_t smem_u32(const void* p){
  uint32_t a;
  asm("{ .reg .u64 t; cvta.to.shared.u64 t, %1; cvt.u32.u64 %0, t; }" : "=r"(a) : "l"(p));
  return a;
}
__device__ __forceinline__ void ldm4(uint32_t* r, uint32_t a){
  asm volatile("ldmatrix.sync.aligned.m8n8.x4.shared.b16 {%0,%1,%2,%3}, [%4];"
    : "=r"(r[0]),"=r"(r[1]),"=r"(r[2]),"=r"(r[3]) : "r"(a));
}
__device__ __forceinline__ void ldm4t(uint32_t* r, uint32_t a){
  asm volatile("ldmatrix.sync.aligned.m8n8.x4.trans.shared.b16 {%0,%1,%2,%3}, [%4];"
    : "=r"(r[0]),"=r"(r[1]),"=r"(r[2]),"=r"(r[3]) : "r"(a));
}
__device__ __forceinline__ void mma_f16(float* c, const uint32_t* a, const uint32_t* b){
  asm volatile("mma.sync.aligned.m16n8k16.row.col.f32.f16.f16.f32 "
    "{%0,%1,%2,%3}, {%4,%5,%6,%7}, {%8,%9}, {%0,%1,%2,%3};"
    : "+f"(c[0]),"+f"(c[1]),"+f"(c[2]),"+f"(c[3])
    : "r"(a[0]),"r"(a[1]),"r"(a[2]),"r"(a[3]), "r"(b[0]),"r"(b[1]));
}
__device__ __forceinline__ uint32_t swA(int r, int c2){
  int u = c2 >> 4;
  u = (u & 8) | ((u ^ (r & 7)) & 7);
  return (uint32_t)(r*256 + (u << 4) + (c2 & 15));
}
__device__ __forceinline__ uint32_t swB128(int r, int c2){   // B tile: 128 rows x 256B
  int u = c2 >> 4;
  u = (u & ~7) | ((u ^ (r & 7)) & 7);
  return (uint32_t)(r*256 + (u << 4) + (c2 & 15));
}

#define SM_ALO 32768
#define SM_B   65536
#define SMEM_TOT 98304      // 96 KB -> 2 CTAs/SM

// 2-term 128-col compute: D = Ahi@B + Alo@B.
__device__ __forceinline__ void mma_compute128(uint32_t sb, float acc[2][4][4], int wid, int lane){
  const int warp_m = wid >> 2, warp_n = wid & 3;
  const int arow = warp_m*32 + (lane & 15);
  const int ac2b = (lane >> 4) << 4;
  const int bgrp = lane >> 3;
  const int bkr  = ((bgrp & 1) << 3) + (lane & 7);
  const int bnc  = warp_n*32 + ((bgrp >> 1) << 3);

  #pragma unroll
  for(int ks = 0; ks < 8; ks++){
    uint32_t bf[4][2], tmp[4];
    #pragma unroll
    for(int np = 0; np < 2; np++){
      uint32_t boff = swB128(ks*16 + bkr, (bnc + np*16)*2);
      ldm4t(tmp, sb + SM_B + boff);
      bf[np*2][0]=tmp[0]; bf[np*2][1]=tmp[1]; bf[np*2+1][0]=tmp[2]; bf[np*2+1][1]=tmp[3];
    }
    uint32_t a[2][4];
    #pragma unroll
    for(int mt = 0; mt < 2; mt++)
      ldm4(a[mt], sb + swA(arow + mt*16, ks*32 + ac2b));
    #pragma unroll
    for(int mt = 0; mt < 2; mt++)
      #pragma unroll
      for(int nt = 0; nt < 4; nt++)
        mma_f16(acc[mt][nt], a[mt], bf[nt]);
    #pragma unroll
    for(int mt = 0; mt < 2; mt++)
      ldm4(a[mt], sb + SM_ALO + swA(arow + mt*16, ks*32 + ac2b));
    #pragma unroll
    for(int mt = 0; mt < 2; mt++)
      #pragma unroll
      for(int nt = 0; nt < 4; nt++)
        mma_f16(acc[mt][nt], a[mt], bf[nt]);
  }
}

__device__ __forceinline__ void fill_B128(char* smem, int tid,
  const __half* __restrict__ Wg, int stride, int col_off){
  for(int ch = tid; ch < 2048; ch += 512){
    int r = ch >> 4, c2 = (ch & 15) * 16;
    uint32_t off = swB128(r, c2);
    *(uint4*)(smem + SM_B + off) = *(const uint4*)(Wg + r*stride + col_off + (c2 >> 1));
  }
}

// epilogue for a 128-col pass: OUT=0 -> g_xlh (fp16), OUT=1 -> g_xr (fp32)
template<int OUT>
__device__ __forceinline__ void ep128(float acc[2][4][4], int bm, int wid, int lane){
  const int warp_m = wid >> 2, warp_n = wid & 3;
  #pragma unroll
  for(int mt = 0; mt < 2; mt++){
    int r0 = bm + warp_m*32 + mt*16 + (lane >> 2);
    #pragma unroll
    for(int nt = 0; nt < 4; nt++){
      int col = warp_n*32 + nt*8 + (lane & 3)*2;
      #pragma unroll
      for(int half = 0; half < 2; half++){
        int grow = r0 + half*8;
        if(grow >= NN) continue;
        float v0 = acc[mt][nt][half*2], v1 = acc[mt][nt][half*2+1];
        if(OUT == 0)
          *(__half2*)(g_xlh + grow*128 + col) = __floats2half2_rn(v0, v1);
        else
          *(float2*)(g_xr + grow*128 + col) = make_float2(v0, v1);
      }
    }
  }
}

#define ZERO_ACC(acc) { _Pragma("unroll") for(int mt=0;mt<2;mt++) _Pragma("unroll") for(int nt=0;nt<4;nt++) _Pragma("unroll") for(int r=0;r<4;r++) acc[mt][nt][r]=0.f; }

// ================= setup: weights->fp16 + x copy/split + edge count =================
__global__ void k_setup(const float* __restrict__ x, const int* __restrict__ ei,
                        const float* __restrict__ Wl, const float* __restrict__ Wr,
                        const float* __restrict__ skW){
  int i = blockIdx.x*blockDim.x + threadIdx.x;
  if(i < 4*32768 + 16384){
    float v;
    if(i < 4*32768){
      int l = i >> 15, rem = i & 32767, k = rem >> 8, n = rem & 255;
      v = (n < 128) ? Wl[l*16384 + k*128 + n] : Wr[l*16384 + k*128 + (n-128)];
    } else {
      v = skW[i - 4*32768];
    }
    g_wh[i] = __float2half_rn(v);
  }
  if(i < NT){
    int d = (i < NE) ? ei[NE + i] : (i - NE);
    atomicAdd(&g_cnt[d], 1);
  }
  if(i >= NN*32) return;
  float4 v = ((const float4*)x)[i];
  ((float4*)g_x)[i] = v;
  __half2 h0, h1, l0, l1;
  h0.x = __float2half_rn(v.x); h0.y = __float2half_rn(v.y);
  h1.x = __float2half_rn(v.z); h1.y = __float2half_rn(v.w);
  l0.x = __float2half_rn(v.x - __half2float(h0.x));
  l0.y = __float2half_rn(v.y - __half2float(h0.y));
  l1.x = __float2half_rn(v.z - __half2float(h1.x));
  l1.y = __float2half_rn(v.w - __half2float(h1.y));
  ((__half2*)g_ahi)[2*i] = h0; ((__half2*)g_ahi)[2*i+1] = h1;
  ((__half2*)g_alo)[2*i] = l0; ((__half2*)g_alo)[2*i+1] = l1;
}
#define SCAN_B 196
__global__ void k_blocksum(){
  __shared__ int sh[256];
  __shared__ int s_last;
  int t = threadIdx.x;
  int i = blockIdx.x*256 + t;
  sh[t] = (i < NN) ? g_cnt[i] : 0; __syncthreads();
  #pragma unroll
  for(int off = 128; off > 0; off >>= 1){
    if(t < off) sh[t] += sh[t+off];
    __syncthreads();
  }
  if(t == 0) g_bsum[blockIdx.x] = sh[0];
  __threadfence();
  if(t == 0){
    int v = atomicAdd(&g_ctr, 1);
    s_last = (v == (int)gridDim.x - 1);
  }
  __syncthreads();
  if(s_last){
    int v = (t < SCAN_B) ? g_bsum[t] : 0;
    sh[t] = v; __syncthreads();
    #pragma unroll
    for(int off = 1; off < 256; off <<= 1){
      int u = (t >= off) ? sh[t-off] : 0;
      __syncthreads(); sh[t] += u; __syncthreads();
    }
    if(t < SCAN_B) g_bpre[t] = sh[t] - v;
    if(t == 255) g_rowptr[NN] = sh[255];
    if(t == 0) g_ctr = 0;
  }
}
__global__ void k_rowptr(){
  __shared__ int sh[256];
  int t = threadIdx.x;
  int i = blockIdx.x*256 + t;
  int v = (i < NN) ? g_cnt[i] : 0;
  sh[t] = v; __syncthreads();
  #pragma unroll
  for(int off = 1; off < 256; off <<= 1){
    int u = (t >= off) ? sh[t-off] : 0;
    __syncthreads(); sh[t] += u; __syncthreads();
  }
  if(i < NN){
    int e = sh[t] - v + g_bpre[blockIdx.x];
    g_rowptr[i] = e; g_fill[i] = e;
  }
}
// batched scatter: 4 edges/thread, independent atomics for MLP
__global__ void k_scatter(const int* __restrict__ ei){
  int base = (blockIdx.x*blockDim.x + threadIdx.x)*4;
  int s[4], d[4], pos[4];
  bool val[4];
  #pragma unroll
  for(int j = 0; j < 4; j++){
    int e = base + j;
    val[j] = e < NT;
    if(val[j]){
      if(e < NE){ s[j] = ei[e]; d[j] = ei[NE + e]; }
      else      { s[j] = d[j] = e - NE; }
    }
  }
  #pragma unroll
  for(int j = 0; j < 4; j++)
    if(val[j]) pos[j] = atomicAdd(&g_fill[d[j]], 1);
  #pragma unroll
  for(int j = 0; j < 4; j++)
    if(val[j]) g_csrc[pos[j]] = s[j];
}

// ================= layer-0 LR GEMM (two 128-col passes, 96KB smem) =================
__global__ void __launch_bounds__(512, 2) k_mma_lr0(){
  extern __shared__ __align__(16) char smem[];
  const int tid = threadIdx.x, wid = tid >> 5, lane = tid & 31;
  const int bm = blockIdx.x * 128;
  const uint32_t sb = smem_u32(smem);
  for(int ch = tid; ch < 2048; ch += 512){
    int r = ch >> 4, c2 = (ch & 15) << 4;
    int grow = bm + r;
    uint32_t off = swA(r, c2);
    uint4 vh = make_uint4(0,0,0,0), vl = vh;
    if(grow < NN){
      vh = *(const uint4*)(g_ahi + grow*128 + (c2 >> 1));
      vl = *(const uint4*)(g_alo + grow*128 + (c2 >> 1));
    }
    *(uint4*)(smem + off)          = vh;
    *(uint4*)(smem + SM_ALO + off) = vl;
  }
  fill_B128(smem, tid, g_wh, 256, 0);         // Wl half
  __syncthreads();
  float acc[2][4][4];
  ZERO_ACC(acc);
  mma_compute128(sb, acc, wid, lane);
  __syncthreads();                            // B reads complete
  ep128<0>(acc, bm, wid, lane);               // overlap: epilogue stores ...
  fill_B128(smem, tid, g_wh, 256, 128);       // ... with Wr-half B fill
  __syncthreads();
  ZERO_ACC(acc);
  mma_compute128(sb, acc, wid, lane);
  ep128<1>(acc, bm, wid, lane);
}

// ================= fused skip-GEMM (+ next-layer LR GEMM, or final FC) =================
template<bool DO_LR>
__global__ void __launch_bounds__(512, 2) k_fused(const float* __restrict__ bias, int next_layer,
                                                  const float* __restrict__ fw,
                                                  const float* __restrict__ fb,
                                                  float* __restrict__ out){
  extern __shared__ __align__(16) char smem[];
  const int tid = threadIdx.x, wid = tid >> 5, lane = tid & 31;
  const int bm = blockIdx.x * 128;
  const uint32_t sb = smem_u32(smem);

  // ---- prologue: A = fp16split(normelu(h)), B = skW ----
  for(int ch = tid; ch < 2048; ch += 512){
    int r = ch >> 4, c2 = (ch & 15) << 4;
    int grow = bm + r;
    uint32_t off = swA(r, c2);
    int c = c2 >> 1;
    __half2 hh[4], ll[4];
    if(grow < NN){
      #pragma unroll
      for(int q = 0; q < 2; q++){
        float4 v  = *(const float4*)(g_h + grow*128 + c + q*4);
        float4 sc = *(const float4*)(g_scale + c + q*4);
        float4 sh = *(const float4*)(g_shift + c + q*4);
        float z0 = fmaf(v.x, sc.x, sh.x); z0 = z0 > 0.f ? z0 : (__expf(z0) - 1.f);
        float z1 = fmaf(v.y, sc.y, sh.y); z1 = z1 > 0.f ? z1 : (__expf(z1) - 1.f);
        float z2 = fmaf(v.z, sc.z, sh.z); z2 = z2 > 0.f ? z2 : (__expf(z2) - 1.f);
        float z3 = fmaf(v.w, sc.w, sh.w); z3 = z3 > 0.f ? z3 : (__expf(z3) - 1.f);
        hh[q*2].x   = __float2half_rn(z0); hh[q*2].y   = __float2half_rn(z1);
        hh[q*2+1].x = __float2half_rn(z2); hh[q*2+1].y = __float2half_rn(z3);
        ll[q*2].x   = __float2half_rn(z0 - __half2float(hh[q*2].x));
        ll[q*2].y   = __float2half_rn(z1 - __half2float(hh[q*2].y));
        ll[q*2+1].x = __float2half_rn(z2 - __half2float(hh[q*2+1].x));
        ll[q*2+1].y = __float2half_rn(z3 - __half2float(hh[q*2+1].y));
      }
    } else {
      #pragma unroll
      for(int q = 0; q < 4; q++){ hh[q].x = hh[q].y = __float2half_rn(0.f); ll[q] = hh[q]; }
    }
    *(uint4*)(smem + off)          = *(uint4*)hh;
    *(uint4*)(smem + SM_ALO + off) = *(uint4*)ll;
  }
  fill_B128(smem, tid, g_wh + 4*32768, 128, 0);
  __syncthreads();

  // ---- skip GEMM ----
  {
    float acc[2][4][4];
    ZERO_ACC(acc);
    mma_compute128(sb, acc, wid, lane);
    __syncthreads();               // A/B reads complete

    const int warp_m = wid >> 2, warp_n = wid & 3;
    #pragma unroll
    for(int mt = 0; mt < 2; mt++){
      int rloc0 = warp_m*32 + mt*16 + (lane >> 2);
      #pragma unroll
      for(int nt = 0; nt < 4; nt++){
        int col = warp_n*32 + nt*8 + (lane & 3)*2;
        #pragma unroll
        for(int half = 0; half < 2; half++){
          int rloc = rloc0 + half*8;
          int grow = bm + rloc;
          float v0 = acc[mt][nt][half*2], v1 = acc[mt][nt][half*2+1];
          if(grow < NN){
            float2 old = *(const float2*)(g_x + grow*128 + col);
            v0 += bias[col]   + old.x;
            v1 += bias[col+1] + old.y;
            *(float2*)(g_x + grow*128 + col) = make_float2(v0, v1);
          } else { v0 = 0.f; v1 = 0.f; }
          if(DO_LR){
            __half2 h, l;
            h.x = __float2half_rn(v0); h.y = __float2half_rn(v1);
            l.x = __float2half_rn(v0 - __half2float(h.x));
            l.y = __float2half_rn(v1 - __half2float(h.y));
            uint32_t off = swA(rloc, col*2);
            *(__half2*)(smem + off)          = h;
            *(__half2*)(smem + SM_ALO + off) = l;
          }
        }
      }
    }
    if(DO_LR)
      fill_B128(smem, tid, g_wh + next_layer*32768, 256, 0);  // Wl half, overlapped
  }
  if(!DO_LR){
    // ---- fused final FC + g_cnt re-zero for next call ----
    __syncthreads();
    int row = bm + (tid >> 2);
    int part = tid & 3;
    int rowc = row < NN ? row : (NN - 1);
    const float4* xp = (const float4*)(g_x + rowc*128 + part*32);
    float s = 0.f;
    #pragma unroll
    for(int q = 0; q < 8; q++){
      float4 v = xp[q];
      float4 w = *(const float4*)(fw + part*32 + q*4);
      s += v.x*w.x + v.y*w.y + v.z*w.z + v.w*w.w;
    }
    s += __shfl_xor_sync(0xffffffffu, s, 1);
    s += __shfl_xor_sync(0xffffffffu, s, 2);
    if(part == 0 && row < NN) out[row] = s + fb[0];
    for(int i = blockIdx.x*512 + tid; i < NN; i += gridDim.x*512)
      g_cnt[i] = 0;
    return;
  }

  __syncthreads();                 // A rewrite + B(Wl) fill visible
  {
    float acc[2][4][4];
    ZERO_ACC(acc);
    mma_compute128(sb, acc, wid, lane);
    __syncthreads();               // B reads complete
    ep128<0>(acc, bm, wid, lane);  // overlap epilogue with Wr B fill
    fill_B128(smem, tid, g_wh + next_layer*32768, 256, 128);
  }
  __syncthreads();
  {
    float acc[2][4][4];
    ZERO_ACC(acc);
    mma_compute128(sb, acc, wid, lane);
    ep128<1>(acc, bm, wid, lane);
  }
}

// ================= GATv2 (proven round-10 form) + fused GraphNorm =================
__device__ __forceinline__ float lrelu(float v){ return v > 0.f ? v : 0.2f*v; }

__global__ void __launch_bounds__(256) k_gat(const float* __restrict__ att,
                                             const float* __restrict__ convb,
                                             const float* __restrict__ gnw,
                                             const float* __restrict__ gnb,
                                             const float* __restrict__ gnms){
  __shared__ float s_sum[8][128];
  __shared__ float s_sq [8][128];
  __shared__ int s_last;
  int tid = threadIdx.x, wid = tid >> 5, lane = tid & 31;
  int node = blockIdx.x*8 + wid;
  int c4 = lane * 4;
  float4 o = make_float4(0.f, 0.f, 0.f, 0.f);

  if(node < NN){
    const float4 xr4 = *(const float4*)(g_xr + node*128 + c4);
    const float4 at4 = *(const float4*)(att + c4);
    int pb = g_rowptr[node], pe = g_rowptr[node+1];

    float m = -3.4e38f, ds = 0.f;
    float a0 = 0.f, a1 = 0.f, a2 = 0.f, a3 = 0.f;

    if(pb < pe){
      int sA = g_csrc[pb];
      uint2 rawN = *(const uint2*)(g_xlh + sA*128 + c4);
      int sB = (pb+1 < pe) ? g_csrc[pb+1] : 0;
      for(int p = pb; p < pe; p++){
        uint2 raw = rawN;
        if(p+1 < pe){
          rawN = *(const uint2*)(g_xlh + sB*128 + c4);
          if(p+2 < pe) sB = g_csrc[p+2];
        }
        float2 f0 = __half22float2(*(__half2*)&raw.x);
        float2 f1 = __half22float2(*(__half2*)&raw.y);
        float t = lrelu(f0.x + xr4.x)*at4.x + lrelu(f0.y + xr4.y)*at4.y
                + lrelu(f1.x + xr4.z)*at4.z + lrelu(f1.y + xr4.w)*at4.w;
        t += __shfl_xor_sync(0xffffffffu, t, 4);
        t += __shfl_xor_sync(0xffffffffu, t, 2);
        t += __shfl_xor_sync(0xffffffffu, t, 1);
        if(t <= m){
          float a = __expf(t - m);
          ds += a;
          a0 = fmaf(a, f0.x, a0); a1 = fmaf(a, f0.y, a1);
          a2 = fmaf(a, f1.x, a2); a3 = fmaf(a, f1.y, a3);
        } else {
          float f = __expf(m - t);
          ds = fmaf(ds, f, 1.f);
          a0 = fmaf(a0, f, f0.x); a1 = fmaf(a1, f, f0.y);
          a2 = fmaf(a2, f, f1.x); a3 = fmaf(a3, f, f1.y);
          m = t;
        }
      }
    }
    float inv = 1.f / ds;
    const float4 bb = *(const float4*)(convb + c4);
    o.x = fmaf(a0, inv, bb.x); o.y = fmaf(a1, inv, bb.y);
    o.z = fmaf(a2, inv, bb.z); o.w = fmaf(a3, inv, bb.w);
    *(float4*)(g_h + node*128 + c4) = o;
  }

  s_sum[wid][c4]   = o.x;     s_sum[wid][c4+1] = o.y;
  s_sum[wid][c4+2] = o.z;     s_sum[wid][c4+3] = o.w;
  s_sq [wid][c4]   = o.x*o.x; s_sq [wid][c4+1] = o.y*o.y;
  s_sq [wid][c4+2] = o.z*o.z; s_sq [wid][c4+3] = o.w*o.w;
  __syncthreads();
  if(tid < 128){
    float s = 0.f, q = 0.f;
    #pragma unroll
    for(int w = 0; w < 8; w++){ s += s_sum[w][tid]; q += s_sq[w][tid]; }
    atomicAdd(&g_stats[tid], s);
    atomicAdd(&g_stats[128 + tid], q);
  }
  __threadfence();
  if(tid == 0){
    int v = atomicAdd(&g_ctr, 1);
    s_last = (v == (int)gridDim.x - 1);
  }
  __syncthreads();
  if(s_last){
    if(tid < 128){
      float sum = g_stats[tid], sq = g_stats[128 + tid];
      float mean = sum * (1.f/(float)NN);
      float mv = gnms[tid] * mean;
      float var = sq * (1.f/(float)NN) - 2.f*mv*mean + mv*mv;
      float sc = gnw[tid] * rsqrtf(var + EPSV);
      g_scale[tid] = sc;
      g_shift[tid] = gnb[tid] - mv*sc;
      g_stats[tid] = 0.f; g_stats[128 + tid] = 0.f;
    }
    if(tid == 0) g_ctr = 0;
  }
}

// ================= launcher =================
extern "C" void kernel_launch(void* const* d_in, const int* in_sizes, int n_in,
                              void* d_out, int out_size){
  const float* x     = (const float*)d_in[0];
  const int*   ei    = (const int*)  d_in[1];
  const float* Wl    = (const float*)d_in[2];
  const float* Wr    = (const float*)d_in[3];
  const float* att   = (const float*)d_in[4];
  const float* convb = (const float*)d_in[5];
  const float* gnw   = (const float*)d_in[6];
  const float* gnb   = (const float*)d_in[7];
  const float* gnms  = (const float*)d_in[8];
  const float* skW   = (const float*)d_in[9];
  const float* skb   = (const float*)d_in[10];
  const float* fcW   = (const float*)d_in[11];
  const float* fcb   = (const float*)d_in[12];
  float* out = (float*)d_out;

  static int cfg_done = 0;
  static cudaStream_t s2;
  static cudaEvent_t evFork, evJoin;
  if(!cfg_done){
    cudaFuncSetAttribute(k_mma_lr0,      cudaFuncAttributeMaxDynamicSharedMemorySize, SMEM_TOT);
    cudaFuncSetAttribute(k_fused<true>,  cudaFuncAttributeMaxDynamicSharedMemorySize, SMEM_TOT);
    cudaFuncSetAttribute(k_fused<false>, cudaFuncAttributeMaxDynamicSharedMemorySize, SMEM_TOT);
    cudaStreamCreateWithFlags(&s2, cudaStreamNonBlocking);
    cudaEventCreateWithFlags(&evFork, cudaEventDisableTiming);
    cudaEventCreateWithFlags(&evJoin, cudaEventDisableTiming);
    cfg_done = 1;
  }

  k_setup<<<(NN*32 + 255)/256, 256>>>(x, ei, Wl, Wr, skW);
  // fork: CSR chain on s2, overlapping with layer-0 GEMM on the main stream
  cudaEventRecord(evFork, 0);
  cudaStreamWaitEvent(s2, evFork, 0);
  k_blocksum<<<SCAN_B, 256, 0, s2>>>();
  k_rowptr  <<<SCAN_B, 256, 0, s2>>>();
  k_scatter <<<(NT/4 + 255)/256, 256, 0, s2>>>(ei);
  cudaEventRecord(evJoin, s2);

  const int MMA_GRID = (NN + 127)/128;       // 391
  const int GAT_GRID = (NN + 7)/8;           // 6250
  k_mma_lr0<<<MMA_GRID, 512, SMEM_TOT>>>();
  cudaStreamWaitEvent(0, evJoin, 0);         // join before first gat
  for(int l = 0; l < 4; l++){
    k_gat<<<GAT_GRID, 256>>>(att + l*HID, convb + l*HID,
                             gnw + l*HID, gnb + l*HID, gnms + l*HID);
    if(l < 3) k_fused<true> <<<MMA_GRID, 512, SMEM_TOT>>>(skb, l + 1, nullptr, nullptr, nullptr);
    else      k_fused<false><<<MMA_GRID, 512, SMEM_TOT>>>(skb, 0, fcW, fcb, out);
  }
}